// round 1
// baseline (speedup 1.0000x reference)
#include <cuda_runtime.h>
#include <cuda_bf16.h>
#include <math.h>

#define D_MODEL 2048
#define INNER   4096
#define NHEADS  64
#define HEADDIM 64
#define D_CONV  4
#define BATCH   2
#define SEQLEN  4096

#define BL (BATCH * SEQLEN)      // 8192

// ---------------- scratch (device globals; no allocation allowed) ----------
__device__ float g_proj[(size_t)BL * INNER];   // in_proj output
__device__ float g_gate[(size_t)BL * INNER];   // sigmoid(gate_proj)
__device__ float g_x[(size_t)BL * INNER];      // conv+silu output X
__device__ float g_comb[(size_t)BL * INNER];   // (C*s + D*X) * gate
__device__ float g_dt[(size_t)BL * NHEADS];    // softplus(dt)

// ---------------- SGEMM: C[M,N] = A[M,K] * W[N,K]^T  (both K-contiguous) ---
// 128x128 block tile, BK=16, 256 threads, 8x8 microtile per thread.
#define BM 128
#define BN 128
#define BK 16

#define EPI_NONE 0
#define EPI_SIGMOID 1

__global__ __launch_bounds__(256, 2)
void sgemm_nt(const float* __restrict__ A, const float* __restrict__ W,
              float* __restrict__ C, int M, int N, int K, int epi)
{
    __shared__ float As[BK][BM];
    __shared__ float Bs[BK][BN];

    const int bm = blockIdx.y * BM;
    const int bn = blockIdx.x * BN;
    const int tid = threadIdx.x;
    const int tx = tid & 15;        // 0..15
    const int ty = tid >> 4;        // 0..15

    float acc[8][8];
#pragma unroll
    for (int i = 0; i < 8; i++)
#pragma unroll
        for (int j = 0; j < 8; j++) acc[i][j] = 0.f;

    // global tile load mapping: each thread loads 2 rows (lr, lr+64), 4 floats each
    const int lr = tid >> 2;          // 0..63
    const int lc = (tid & 3) * 4;     // 0,4,8,12
    const float* Ap = A + (size_t)(bm + lr) * K + lc;
    const float* Wp = W + (size_t)(bn + lr) * K + lc;

    for (int k0 = 0; k0 < K; k0 += BK) {
#pragma unroll
        for (int w = 0; w < 2; w++) {
            float4 va = *reinterpret_cast<const float4*>(Ap + (size_t)(w * 64) * K + k0);
            float4 vb = *reinterpret_cast<const float4*>(Wp + (size_t)(w * 64) * K + k0);
            int r = lr + w * 64;
            As[lc + 0][r] = va.x; As[lc + 1][r] = va.y;
            As[lc + 2][r] = va.z; As[lc + 3][r] = va.w;
            Bs[lc + 0][r] = vb.x; Bs[lc + 1][r] = vb.y;
            Bs[lc + 2][r] = vb.z; Bs[lc + 3][r] = vb.w;
        }
        __syncthreads();

#pragma unroll
        for (int kk = 0; kk < BK; kk++) {
            float4 a0 = *reinterpret_cast<const float4*>(&As[kk][ty * 8]);
            float4 a1 = *reinterpret_cast<const float4*>(&As[kk][ty * 8 + 4]);
            float4 b0 = *reinterpret_cast<const float4*>(&Bs[kk][tx * 8]);
            float4 b1 = *reinterpret_cast<const float4*>(&Bs[kk][tx * 8 + 4]);
            float af[8] = {a0.x, a0.y, a0.z, a0.w, a1.x, a1.y, a1.z, a1.w};
            float bf[8] = {b0.x, b0.y, b0.z, b0.w, b1.x, b1.y, b1.z, b1.w};
#pragma unroll
            for (int i = 0; i < 8; i++)
#pragma unroll
                for (int j = 0; j < 8; j++)
                    acc[i][j] = fmaf(af[i], bf[j], acc[i][j]);
        }
        __syncthreads();
    }

#pragma unroll
    for (int i = 0; i < 8; i++) {
        int row = bm + ty * 8 + i;
        float* Crow = C + (size_t)row * N + bn + tx * 8;
#pragma unroll
        for (int j = 0; j < 8; j += 4) {
            float4 v;
            v.x = acc[i][j + 0]; v.y = acc[i][j + 1];
            v.z = acc[i][j + 2]; v.w = acc[i][j + 3];
            if (epi == EPI_SIGMOID) {
                v.x = 1.f / (1.f + expf(-v.x));
                v.y = 1.f / (1.f + expf(-v.y));
                v.z = 1.f / (1.f + expf(-v.z));
                v.w = 1.f / (1.f + expf(-v.w));
            }
            *reinterpret_cast<float4*>(Crow + j) = v;
        }
    }
}

// ---------------- conv(K=4, causal, depthwise) + SiLU + dt(softplus) -------
// one block per (b,l); 256 threads
__global__ __launch_bounds__(256)
void conv_dt_kernel(const float* __restrict__ proj,
                    const float* __restrict__ cw,   // (INNER, 4)
                    const float* __restrict__ cb,   // (INNER,)
                    const float* __restrict__ dtw,  // (NHEADS, HEADDIM)
                    const float* __restrict__ dtb,  // (NHEADS,)
                    float* __restrict__ Xout,
                    float* __restrict__ dt_out)
{
    const int bl = blockIdx.x;
    const int l = bl % SEQLEN;
    __shared__ float sx[INNER];
    __shared__ float spart[NHEADS][4];

    const int tid = threadIdx.x;
    const float* base = proj + (size_t)bl * INNER;

    for (int c = tid; c < INNER; c += 256) {
        float accv = cb[c];
#pragma unroll
        for (int k = 0; k < D_CONV; k++) {
            int ll = l + k - (D_CONV - 1);
            float xv = (ll >= 0) ? base[(ptrdiff_t)(k - (D_CONV - 1)) * INNER + c] : 0.f;
            accv = fmaf(cw[c * D_CONV + k], xv, accv);
        }
        float s = accv / (1.f + expf(-accv));   // SiLU
        sx[c] = s;
        Xout[(size_t)bl * INNER + c] = s;
    }
    __syncthreads();

    // dt: head-wise reduction, 4 threads per head
    {
        int h = tid >> 2;
        int part = tid & 3;
        float sum = 0.f;
        int p0 = part * 16;
#pragma unroll
        for (int p = 0; p < 16; p++)
            sum = fmaf(sx[h * HEADDIM + p0 + p], dtw[h * HEADDIM + p0 + p], sum);
        spart[h][part] = sum;
    }
    __syncthreads();
    if (tid < NHEADS) {
        float v = spart[tid][0] + spart[tid][1] + spart[tid][2] + spart[tid][3] + dtb[tid];
        float sp = (v > 20.f) ? v : log1pf(expf(v));
        dt_out[(size_t)bl * NHEADS + tid] = sp;
    }
}

// ---------------- SSM scan + output fusion ---------------------------------
// one block per (b,h); blockDim (64,16): x = p channel, y = L segment
#define NSEG 16
#define SEG (SEQLEN / NSEG)     // 256

__global__ __launch_bounds__(1024, 1)
void scan_kernel(const float* __restrict__ X,
                 const float* __restrict__ dt,
                 const float* __restrict__ gate,
                 const float* __restrict__ A_log,
                 const float* __restrict__ Bv,
                 const float* __restrict__ Cv,
                 const float* __restrict__ Dv,
                 float* __restrict__ comb)
{
    const int bh = blockIdx.x;
    const int h = bh % NHEADS;
    const int b = bh / NHEADS;
    const int p = threadIdx.x;        // 0..63
    const int s = threadIdx.y;        // 0..15

    const int hp = h * HEADDIM + p;
    const float acoef = -expf(A_log[hp]);
    const float Bc = Bv[hp];
    const float Cc = Cv[hp];
    const float Dc = Dv[hp];

    const size_t baseX = (size_t)b * SEQLEN * INNER + (size_t)h * HEADDIM + p;
    const size_t baseDt = (size_t)b * SEQLEN * NHEADS + h;
    const int l0 = s * SEG;

    __shared__ float agg_a[NSEG][HEADDIM];
    __shared__ float agg_u[NSEG][HEADDIM];
    __shared__ float pre[NSEG][HEADDIM];

    // pass 1: segment summary (product of a, driven state assuming s_in = 0)
    float ap = 1.f, ss = 0.f;
    for (int i = 0; i < SEG; i++) {
        int l = l0 + i;
        float d = dt[baseDt + (size_t)l * NHEADS];
        float xv = X[baseX + (size_t)l * INNER];
        float a = expf(d * acoef);
        float u = d * Bc * xv;
        ap *= a;
        ss = fmaf(a, ss, u);
    }
    agg_a[s][p] = ap;
    agg_u[s][p] = ss;
    __syncthreads();

    // scan the 16 segment summaries (64 threads, one per p)
    if (s == 0) {
        float st = 0.f;
#pragma unroll
        for (int j = 0; j < NSEG; j++) {
            pre[j][p] = st;
            st = fmaf(agg_a[j][p], st, agg_u[j][p]);
        }
    }
    __syncthreads();

    // pass 2: replay with carry-in, fuse y = C*s + D*X, multiply by gate
    float sprev = pre[s][p];
    for (int i = 0; i < SEG; i++) {
        int l = l0 + i;
        float d = dt[baseDt + (size_t)l * NHEADS];
        size_t idx = baseX + (size_t)l * INNER;
        float xv = X[idx];
        float a = expf(d * acoef);
        float u = d * Bc * xv;
        sprev = fmaf(a, sprev, u);
        float y = fmaf(Cc, sprev, Dc * xv);
        comb[idx] = y * gate[idx];
    }
}

// ---------------- launch ----------------------------------------------------
extern "C" void kernel_launch(void* const* d_in, const int* in_sizes, int n_in,
                              void* d_out, int out_size)
{
    const float* hidden   = (const float*)d_in[0];
    const float* in_w     = (const float*)d_in[1];
    const float* gate_w   = (const float*)d_in[2];
    const float* out_w    = (const float*)d_in[3];
    const float* conv_w   = (const float*)d_in[4];
    const float* conv_b   = (const float*)d_in[5];
    const float* dt_w     = (const float*)d_in[6];
    const float* dt_b     = (const float*)d_in[7];
    const float* A_log    = (const float*)d_in[8];
    const float* Bv       = (const float*)d_in[9];
    const float* Cv       = (const float*)d_in[10];
    const float* Dv       = (const float*)d_in[11];
    float* out            = (float*)d_out;

    float *proj, *gatebuf, *xbuf, *combbuf, *dtbuf;
    cudaGetSymbolAddress((void**)&proj,    g_proj);
    cudaGetSymbolAddress((void**)&gatebuf, g_gate);
    cudaGetSymbolAddress((void**)&xbuf,    g_x);
    cudaGetSymbolAddress((void**)&combbuf, g_comb);
    cudaGetSymbolAddress((void**)&dtbuf,   g_dt);

    // 1) in_proj GEMM: (8192,2048) x (4096,2048)^T
    {
        dim3 grid(INNER / BN, BL / BM);
        sgemm_nt<<<grid, 256>>>(hidden, in_w, proj, BL, INNER, D_MODEL, EPI_NONE);
    }
    // 2) gate GEMM + sigmoid epilogue
    {
        dim3 grid(INNER / BN, BL / BM);
        sgemm_nt<<<grid, 256>>>(hidden, gate_w, gatebuf, BL, INNER, D_MODEL, EPI_SIGMOID);
    }
    // 3) conv + silu + dt
    conv_dt_kernel<<<BL, 256>>>(proj, conv_w, conv_b, dt_w, dt_b, xbuf, dtbuf);
    // 4) SSM scan fused with y & gate
    {
        dim3 blk(HEADDIM, NSEG);
        scan_kernel<<<BATCH * NHEADS, blk>>>(xbuf, dtbuf, gatebuf, A_log, Bv, Cv, Dv, combbuf);
    }
    // 5) out_proj GEMM: (8192,4096) x (2048,4096)^T
    {
        dim3 grid(D_MODEL / BN, BL / BM);
        sgemm_nt<<<grid, 256>>>(combbuf, out_w, out, BL, D_MODEL, INNER, EPI_NONE);
    }
}

// round 3
// speedup vs baseline: 3.3650x; 3.3650x over previous
#include <cuda.h>
#include <cuda_runtime.h>
#include <cuda_bf16.h>
#include <math.h>

#define D_MODEL 2048
#define INNER   4096
#define NHEADS  64
#define HEADDIM 64
#define D_CONV  4
#define BATCH   2
#define SEQLEN  4096
#define BL (BATCH * SEQLEN)      // 8192

// ---------------- scratch (device globals; no allocation allowed) ----------
__device__ float g_proj[(size_t)BL * INNER];            // in_proj output (fp32)
__device__ float g_gate[(size_t)BL * INNER];            // sigmoid(gate_proj)
__device__ float g_x[(size_t)BL * INNER];               // conv+silu output X
__device__ float g_dt[(size_t)BL * NHEADS];             // softplus(dt)

__device__ __nv_bfloat16 g_hh[(size_t)BL * D_MODEL];    // hidden hi
__device__ __nv_bfloat16 g_hl[(size_t)BL * D_MODEL];    // hidden lo
__device__ __nv_bfloat16 g_iwh[(size_t)INNER * D_MODEL];
__device__ __nv_bfloat16 g_iwl[(size_t)INNER * D_MODEL];
__device__ __nv_bfloat16 g_gwh[(size_t)INNER * D_MODEL];
__device__ __nv_bfloat16 g_gwl[(size_t)INNER * D_MODEL];
__device__ __nv_bfloat16 g_owh[(size_t)D_MODEL * INNER];
__device__ __nv_bfloat16 g_owl[(size_t)D_MODEL * INNER];
__device__ __nv_bfloat16 g_ch[(size_t)BL * INNER];      // comb hi
__device__ __nv_bfloat16 g_cl[(size_t)BL * INNER];      // comb lo

// ===================== PTX helpers ==========================================
__device__ __forceinline__ uint32_t smem_to_u32(const void* smem_ptr) {
    uint32_t addr;
    asm("{ .reg .u64 tmp; cvta.to.shared.u64 tmp, %1; cvt.u32.u64 %0, tmp; }"
        : "=r"(addr) : "l"(smem_ptr));
    return addr;
}

#define MBARRIER_INIT(mbar, count) \
    asm volatile("mbarrier.init.shared.b64 [%0], %1;" \
        :: "r"((uint32_t)(mbar)), "r"((uint32_t)(count)) : "memory")

#define MBARRIER_EXPECT_TX(mbar, bytes) \
    asm volatile("mbarrier.arrive.expect_tx.shared.b64 _, [%0], %1;" \
        :: "r"((uint32_t)(mbar)), "r"((uint32_t)(bytes)) : "memory")

#define MBARRIER_WAIT_PARITY(mbar, parity) do { \
    uint32_t _m = (uint32_t)(mbar); uint32_t _p = (uint32_t)(parity); uint32_t _d; \
    asm volatile( \
        "{\n\t.reg .pred p;\n\t" \
        "mbarrier.try_wait.parity.acquire.cta.shared::cta.b64 p, [%1], %2;\n\t" \
        "selp.b32 %0, 1, 0, p;\n\t}" \
        : "=r"(_d) : "r"(_m), "r"(_p) : "memory"); \
    if (!_d) { \
        asm volatile( \
            "{\n\t.reg .pred P1;\n\t" \
            "WAIT_LOOP_%=:\n\t" \
            "mbarrier.try_wait.parity.acquire.cta.shared::cta.b64 P1, [%0], %1, 0x989680;\n\t" \
            "@P1 bra.uni WAIT_DONE_%=;\n\t" \
            "bra.uni WAIT_LOOP_%=;\n\t" \
            "WAIT_DONE_%=:\n\t}" \
            :: "r"(_m), "r"(_p) : "memory"); \
    } \
} while (0)

#define TMA2D(smemaddr, tmapptr, cx, cy, mbar) \
    asm volatile( \
        "cp.async.bulk.tensor.2d.shared::cta.global.tile.mbarrier::complete_tx::bytes " \
        "[%0], [%1, {%2, %3}], [%4];" \
        :: "r"((uint32_t)(smemaddr)), "l"(tmapptr), "r"((int)(cx)), "r"((int)(cy)), \
           "r"((uint32_t)(mbar)) : "memory")

__device__ __forceinline__ void ldsm_x4(uint32_t* r, uint32_t addr) {
    asm volatile("ldmatrix.sync.aligned.m8n8.x4.shared.b16 {%0,%1,%2,%3}, [%4];"
        : "=r"(r[0]), "=r"(r[1]), "=r"(r[2]), "=r"(r[3]) : "r"(addr));
}

__device__ __forceinline__ void mma16816(float* d, const uint32_t* a, const uint32_t* b) {
    asm volatile(
        "mma.sync.aligned.m16n8k16.row.col.f32.bf16.bf16.f32 "
        "{%0,%1,%2,%3}, {%4,%5,%6,%7}, {%8,%9}, {%0,%1,%2,%3};"
        : "+f"(d[0]), "+f"(d[1]), "+f"(d[2]), "+f"(d[3])
        : "r"(a[0]), "r"(a[1]), "r"(a[2]), "r"(a[3]), "r"(b[0]), "r"(b[1]));
}

#define SWZ(o) ((o) ^ (((o) >> 3) & 0x70))

// ===================== HMMA GEMM =============================================
// C[M,Ntotal] = (Ah+Al)[M,K] * (Bh+Bl)[N,K]^T, 3-term bf16 split, fp32 acc.
// Tile 128(M) x 128(N), KC=64, 3-stage TMA pipeline, 8 warps (2x4).
#define TILE_M 128
#define TILE_N 128
#define KC 64
#define SOFF_AH 0
#define SOFF_AL 16384
#define SOFF_BH 32768
#define SOFF_BL 49152
#define STAGE_BYTES 65536
#define NSTAGE 3
#define GEMM_SMEM (1024 + NSTAGE * STAGE_BYTES)

__global__ __launch_bounds__(256, 1)
void hmma_gemm(const __grid_constant__ CUtensorMap tAh,
               const __grid_constant__ CUtensorMap tAl,
               const __grid_constant__ CUtensorMap tBh,
               const __grid_constant__ CUtensorMap tBl,
               float* __restrict__ C, int Ntotal, int K, int epi)
{
    extern __shared__ __align__(1024) char smem[];
    const uint32_t sb = smem_to_u32(smem);
    const uint32_t sdata = sb + 1024;
    const int tid = threadIdx.x;
    const int wid = tid >> 5;
    const int lane = tid & 31;
    const int wm = wid >> 2;          // 0..1   (64 rows each)
    const int wn = wid & 3;           // 0..3   (32 cols each)
    const int bm = blockIdx.y * TILE_M;
    const int bn = blockIdx.x * TILE_N;

    uint32_t full[NSTAGE];
#pragma unroll
    for (int s = 0; s < NSTAGE; s++) full[s] = sb + 64 + s * 16;

    if (tid == 0) {
#pragma unroll
        for (int s = 0; s < NSTAGE; s++) MBARRIER_INIT(full[s], 1);
    }
    __syncthreads();

    const int NC = K / KC;

    // prologue: stages 0..2
    if (tid == 0) {
#pragma unroll
        for (int s = 0; s < NSTAGE; s++) {
            if (s < NC) {
                uint32_t st = sdata + s * STAGE_BYTES;
                MBARRIER_EXPECT_TX(full[s], STAGE_BYTES);
                TMA2D(st + SOFF_AH, &tAh, s * KC, bm, full[s]);
                TMA2D(st + SOFF_AL, &tAl, s * KC, bm, full[s]);
                TMA2D(st + SOFF_BH, &tBh, s * KC, bn, full[s]);
                TMA2D(st + SOFF_BL, &tBl, s * KC, bn, full[s]);
            }
        }
    }

    // per-thread ldmatrix base offsets (within a stage tile, before k-step add)
    uint32_t abase[4], bbase[2];
#pragma unroll
    for (int mt = 0; mt < 4; mt++) {
        int row = wm * 64 + mt * 16 + (lane & 15);
        abase[mt] = (uint32_t)(row * 128 + ((lane >> 4) * 16));
    }
#pragma unroll
    for (int q = 0; q < 2; q++) {
        int row = wn * 32 + q * 16 + ((lane >> 4) << 3) + (lane & 7);
        bbase[q] = (uint32_t)(row * 128 + (((lane >> 3) & 1) * 16));
    }

    float acc[4][4][4];
#pragma unroll
    for (int mt = 0; mt < 4; mt++)
#pragma unroll
        for (int nt = 0; nt < 4; nt++)
#pragma unroll
            for (int k = 0; k < 4; k++) acc[mt][nt][k] = 0.f;

    int ph[NSTAGE];
#pragma unroll
    for (int s = 0; s < NSTAGE; s++) ph[s] = 0;

    for (int c = 0; c < NC; c++) {
        const int s = c % NSTAGE;
        const uint32_t st = sdata + s * STAGE_BYTES;
        MBARRIER_WAIT_PARITY(full[s], ph[s]);
        ph[s] ^= 1;

#pragma unroll
        for (int ks = 0; ks < 4; ks++) {
            const uint32_t kb = ks * 32;
            uint32_t ah[4][4], al[4][4], bh[2][4], bl[2][4];
#pragma unroll
            for (int mt = 0; mt < 4; mt++) {
                uint32_t off = SWZ(abase[mt] + kb);
                ldsm_x4(ah[mt], st + SOFF_AH + off);
                ldsm_x4(al[mt], st + SOFF_AL + off);
            }
#pragma unroll
            for (int q = 0; q < 2; q++) {
                uint32_t off = SWZ(bbase[q] + kb);
                ldsm_x4(bh[q], st + SOFF_BH + off);
                ldsm_x4(bl[q], st + SOFF_BL + off);
            }
#pragma unroll
            for (int mt = 0; mt < 4; mt++) {
#pragma unroll
                for (int nt = 0; nt < 4; nt++) {
                    const uint32_t* Bh = &bh[nt >> 1][(nt & 1) * 2];
                    const uint32_t* Bl = &bl[nt >> 1][(nt & 1) * 2];
                    mma16816(acc[mt][nt], ah[mt], Bh);
                    mma16816(acc[mt][nt], ah[mt], Bl);
                    mma16816(acc[mt][nt], al[mt], Bh);
                }
            }
        }
        __syncthreads();   // all reads of stage s done
        if (tid == 0 && c + NSTAGE < NC) {
            MBARRIER_EXPECT_TX(full[s], STAGE_BYTES);
            TMA2D(st + SOFF_AH, &tAh, (c + NSTAGE) * KC, bm, full[s]);
            TMA2D(st + SOFF_AL, &tAl, (c + NSTAGE) * KC, bm, full[s]);
            TMA2D(st + SOFF_BH, &tBh, (c + NSTAGE) * KC, bn, full[s]);
            TMA2D(st + SOFF_BL, &tBl, (c + NSTAGE) * KC, bn, full[s]);
        }
    }

    // epilogue: each quad's float2 pairs form full 32B sectors
    const int g = lane >> 2;
    const int nq = (lane & 3) * 2;
#pragma unroll
    for (int mt = 0; mt < 4; mt++) {
        int r0 = bm + wm * 64 + mt * 16 + g;
#pragma unroll
        for (int nt = 0; nt < 4; nt++) {
            int cc = bn + wn * 32 + nt * 8 + nq;
            float2 v0 = make_float2(acc[mt][nt][0], acc[mt][nt][1]);
            float2 v1 = make_float2(acc[mt][nt][2], acc[mt][nt][3]);
            if (epi == 1) {
                v0.x = 1.f / (1.f + expf(-v0.x));
                v0.y = 1.f / (1.f + expf(-v0.y));
                v1.x = 1.f / (1.f + expf(-v1.x));
                v1.y = 1.f / (1.f + expf(-v1.y));
            }
            *reinterpret_cast<float2*>(C + (size_t)r0 * Ntotal + cc) = v0;
            *reinterpret_cast<float2*>(C + (size_t)(r0 + 8) * Ntotal + cc) = v1;
        }
    }
}

// ===================== split fp32 -> bf16 hi/lo =============================
__global__ __launch_bounds__(256)
void split_hi_lo(const float* __restrict__ x, __nv_bfloat16* __restrict__ hi,
                 __nv_bfloat16* __restrict__ lo, int n)
{
    int i = (blockIdx.x * 256 + threadIdx.x) * 4;
    if (i >= n) return;
    float4 v = *reinterpret_cast<const float4*>(x + i);
    __nv_bfloat16 h0 = __float2bfloat16(v.x);
    __nv_bfloat16 h1 = __float2bfloat16(v.y);
    __nv_bfloat16 h2 = __float2bfloat16(v.z);
    __nv_bfloat16 h3 = __float2bfloat16(v.w);
    __nv_bfloat16 l0 = __float2bfloat16(v.x - __bfloat162float(h0));
    __nv_bfloat16 l1 = __float2bfloat16(v.y - __bfloat162float(h1));
    __nv_bfloat16 l2 = __float2bfloat16(v.z - __bfloat162float(h2));
    __nv_bfloat16 l3 = __float2bfloat16(v.w - __bfloat162float(h3));
    *reinterpret_cast<__nv_bfloat162*>(hi + i)     = __nv_bfloat162(h0, h1);
    *reinterpret_cast<__nv_bfloat162*>(hi + i + 2) = __nv_bfloat162(h2, h3);
    *reinterpret_cast<__nv_bfloat162*>(lo + i)     = __nv_bfloat162(l0, l1);
    *reinterpret_cast<__nv_bfloat162*>(lo + i + 2) = __nv_bfloat162(l2, l3);
}

// ---------------- conv(K=4, causal, depthwise) + SiLU + dt(softplus) -------
__global__ __launch_bounds__(256)
void conv_dt_kernel(const float* __restrict__ proj,
                    const float* __restrict__ cw,
                    const float* __restrict__ cb,
                    const float* __restrict__ dtw,
                    const float* __restrict__ dtb,
                    float* __restrict__ Xout,
                    float* __restrict__ dt_out)
{
    const int bl = blockIdx.x;
    const int l = bl % SEQLEN;
    __shared__ float sx[INNER];
    __shared__ float spart[NHEADS][4];

    const int tid = threadIdx.x;
    const float* base = proj + (size_t)bl * INNER;

    for (int c = tid; c < INNER; c += 256) {
        float accv = cb[c];
#pragma unroll
        for (int k = 0; k < D_CONV; k++) {
            int ll = l + k - (D_CONV - 1);
            float xv = (ll >= 0) ? base[(ptrdiff_t)(k - (D_CONV - 1)) * INNER + c] : 0.f;
            accv = fmaf(cw[c * D_CONV + k], xv, accv);
        }
        float s = accv / (1.f + expf(-accv));
        sx[c] = s;
        Xout[(size_t)bl * INNER + c] = s;
    }
    __syncthreads();

    {
        int h = tid >> 2;
        int part = tid & 3;
        float sum = 0.f;
        int p0 = part * 16;
#pragma unroll
        for (int p = 0; p < 16; p++)
            sum = fmaf(sx[h * HEADDIM + p0 + p], dtw[h * HEADDIM + p0 + p], sum);
        spart[h][part] = sum;
    }
    __syncthreads();
    if (tid < NHEADS) {
        float v = spart[tid][0] + spart[tid][1] + spart[tid][2] + spart[tid][3] + dtb[tid];
        float sp = (v > 20.f) ? v : log1pf(expf(v));
        dt_out[(size_t)bl * NHEADS + tid] = sp;
    }
}

// ---------------- SSM scan + output fusion (emits bf16 hi/lo) ---------------
#define NSEG 16
#define SEG (SEQLEN / NSEG)     // 256

__global__ __launch_bounds__(1024, 1)
void scan_kernel(const float* __restrict__ X,
                 const float* __restrict__ dt,
                 const float* __restrict__ gate,
                 const float* __restrict__ A_log,
                 const float* __restrict__ Bv,
                 const float* __restrict__ Cv,
                 const float* __restrict__ Dv,
                 __nv_bfloat16* __restrict__ ch,
                 __nv_bfloat16* __restrict__ cl)
{
    const int bh = blockIdx.x;
    const int h = bh % NHEADS;
    const int b = bh / NHEADS;
    const int p = threadIdx.x;
    const int s = threadIdx.y;

    const int hp = h * HEADDIM + p;
    const float acoef = -expf(A_log[hp]);
    const float Bc = Bv[hp];
    const float Cc = Cv[hp];
    const float Dc = Dv[hp];

    const size_t baseX = (size_t)b * SEQLEN * INNER + (size_t)h * HEADDIM + p;
    const size_t baseDt = (size_t)b * SEQLEN * NHEADS + h;
    const int l0 = s * SEG;

    __shared__ float agg_a[NSEG][HEADDIM];
    __shared__ float agg_u[NSEG][HEADDIM];
    __shared__ float pre[NSEG][HEADDIM];

    float ap = 1.f, ss = 0.f;
    for (int i = 0; i < SEG; i++) {
        int l = l0 + i;
        float d = dt[baseDt + (size_t)l * NHEADS];
        float xv = X[baseX + (size_t)l * INNER];
        float a = expf(d * acoef);
        float u = d * Bc * xv;
        ap *= a;
        ss = fmaf(a, ss, u);
    }
    agg_a[s][p] = ap;
    agg_u[s][p] = ss;
    __syncthreads();

    if (s == 0) {
        float st = 0.f;
#pragma unroll
        for (int j = 0; j < NSEG; j++) {
            pre[j][p] = st;
            st = fmaf(agg_a[j][p], st, agg_u[j][p]);
        }
    }
    __syncthreads();

    float sprev = pre[s][p];
    for (int i = 0; i < SEG; i++) {
        int l = l0 + i;
        float d = dt[baseDt + (size_t)l * NHEADS];
        size_t idx = baseX + (size_t)l * INNER;
        float xv = X[idx];
        float a = expf(d * acoef);
        float u = d * Bc * xv;
        sprev = fmaf(a, sprev, u);
        float y = fmaf(Cc, sprev, Dc * xv) * gate[idx];
        __nv_bfloat16 hpart = __float2bfloat16(y);
        ch[idx] = hpart;
        cl[idx] = __float2bfloat16(y - __bfloat162float(hpart));
    }
}

// ===================== host side ============================================
typedef CUresult (*TmEncodeFn)(CUtensorMap*, CUtensorMapDataType, cuuint32_t,
                               void*, const cuuint64_t*, const cuuint64_t*,
                               const cuuint32_t*, const cuuint32_t*,
                               CUtensorMapInterleave, CUtensorMapSwizzle,
                               CUtensorMapL2promotion, CUtensorMapFloatOOBfill);

static void make_tm(TmEncodeFn fn, CUtensorMap* tm, const void* ptr,
                    int rows, int K)
{
    cuuint64_t dims[2]    = {(cuuint64_t)K, (cuuint64_t)rows};
    cuuint64_t strides[1] = {(cuuint64_t)K * 2};
    cuuint32_t box[2]     = {64u, 128u};
    cuuint32_t es[2]      = {1u, 1u};
    fn(tm, CU_TENSOR_MAP_DATA_TYPE_BFLOAT16, 2, (void*)ptr,
       dims, strides, box, es,
       CU_TENSOR_MAP_INTERLEAVE_NONE, CU_TENSOR_MAP_SWIZZLE_128B,
       CU_TENSOR_MAP_L2_PROMOTION_L2_128B, CU_TENSOR_MAP_FLOAT_OOB_FILL_NONE);
}

extern "C" void kernel_launch(void* const* d_in, const int* in_sizes, int n_in,
                              void* d_out, int out_size)
{
    const float* hidden = (const float*)d_in[0];
    const float* in_w   = (const float*)d_in[1];
    const float* gate_w = (const float*)d_in[2];
    const float* out_w  = (const float*)d_in[3];
    const float* conv_w = (const float*)d_in[4];
    const float* conv_b = (const float*)d_in[5];
    const float* dt_w   = (const float*)d_in[6];
    const float* dt_b   = (const float*)d_in[7];
    const float* A_log  = (const float*)d_in[8];
    const float* Bv     = (const float*)d_in[9];
    const float* Cv     = (const float*)d_in[10];
    const float* Dv     = (const float*)d_in[11];
    float* out          = (float*)d_out;

    float *proj, *gatebuf, *xbuf, *dtbuf;
    __nv_bfloat16 *hh, *hl, *iwh, *iwl, *gwh, *gwl, *owh, *owl, *ch, *cl;
    cudaGetSymbolAddress((void**)&proj,    g_proj);
    cudaGetSymbolAddress((void**)&gatebuf, g_gate);
    cudaGetSymbolAddress((void**)&xbuf,    g_x);
    cudaGetSymbolAddress((void**)&dtbuf,   g_dt);
    cudaGetSymbolAddress((void**)&hh,  g_hh);
    cudaGetSymbolAddress((void**)&hl,  g_hl);
    cudaGetSymbolAddress((void**)&iwh, g_iwh);
    cudaGetSymbolAddress((void**)&iwl, g_iwl);
    cudaGetSymbolAddress((void**)&gwh, g_gwh);
    cudaGetSymbolAddress((void**)&gwl, g_gwl);
    cudaGetSymbolAddress((void**)&owh, g_owh);
    cudaGetSymbolAddress((void**)&owl, g_owl);
    cudaGetSymbolAddress((void**)&ch,  g_ch);
    cudaGetSymbolAddress((void**)&cl,  g_cl);

    TmEncodeFn enc = nullptr;
    {
        void* p = nullptr;
        cudaDriverEntryPointQueryResult qr;
        cudaGetDriverEntryPointByVersion("cuTensorMapEncodeTiled", &p, 12000,
                                         cudaEnableDefault, &qr);
        enc = (TmEncodeFn)p;
    }

    // splits
    {
        int n;
        n = BL * D_MODEL;        split_hi_lo<<<n / 1024, 256>>>(hidden, hh, hl, n);
        n = INNER * D_MODEL;     split_hi_lo<<<n / 1024, 256>>>(in_w,   iwh, iwl, n);
        n = INNER * D_MODEL;     split_hi_lo<<<n / 1024, 256>>>(gate_w, gwh, gwl, n);
        n = D_MODEL * INNER;     split_hi_lo<<<n / 1024, 256>>>(out_w,  owh, owl, n);
    }

    CUtensorMap tm_hh, tm_hl, tm_iwh, tm_iwl, tm_gwh, tm_gwl, tm_owh, tm_owl, tm_ch, tm_cl;
    make_tm(enc, &tm_hh,  hh,  BL,      D_MODEL);
    make_tm(enc, &tm_hl,  hl,  BL,      D_MODEL);
    make_tm(enc, &tm_iwh, iwh, INNER,   D_MODEL);
    make_tm(enc, &tm_iwl, iwl, INNER,   D_MODEL);
    make_tm(enc, &tm_gwh, gwh, INNER,   D_MODEL);
    make_tm(enc, &tm_gwl, gwl, INNER,   D_MODEL);
    make_tm(enc, &tm_owh, owh, D_MODEL, INNER);
    make_tm(enc, &tm_owl, owl, D_MODEL, INNER);
    make_tm(enc, &tm_ch,  ch,  BL,      INNER);
    make_tm(enc, &tm_cl,  cl,  BL,      INNER);

    cudaFuncSetAttribute(hmma_gemm, cudaFuncAttributeMaxDynamicSharedMemorySize, GEMM_SMEM);

    // 1) in_proj: (8192 x 2048) @ (4096 x 2048)^T -> proj
    {
        dim3 grid(INNER / TILE_N, BL / TILE_M);
        hmma_gemm<<<grid, 256, GEMM_SMEM>>>(tm_hh, tm_hl, tm_iwh, tm_iwl,
                                            proj, INNER, D_MODEL, 0);
    }
    // 2) gate: same shapes, sigmoid epilogue
    {
        dim3 grid(INNER / TILE_N, BL / TILE_M);
        hmma_gemm<<<grid, 256, GEMM_SMEM>>>(tm_hh, tm_hl, tm_gwh, tm_gwl,
                                            gatebuf, INNER, D_MODEL, 1);
    }
    // 3) conv + silu + dt
    conv_dt_kernel<<<BL, 256>>>(proj, conv_w, conv_b, dt_w, dt_b, xbuf, dtbuf);
    // 4) SSM scan fused with y, gate, and bf16 split
    {
        dim3 blk(HEADDIM, NSEG);
        scan_kernel<<<BATCH * NHEADS, blk>>>(xbuf, dtbuf, gatebuf, A_log, Bv, Cv, Dv, ch, cl);
    }
    // 5) out_proj: (8192 x 4096) @ (2048 x 4096)^T -> out
    {
        dim3 grid(D_MODEL / TILE_N, BL / TILE_M);
        hmma_gemm<<<grid, 256, GEMM_SMEM>>>(tm_ch, tm_cl, tm_owh, tm_owl,
                                            out, D_MODEL, INNER, 0);
    }
}

// round 4
// speedup vs baseline: 4.6330x; 1.3768x over previous
#include <cuda.h>
#include <cuda_runtime.h>
#include <cuda_fp16.h>
#include <math.h>

#define D_MODEL 2048
#define INNER   4096
#define NHEADS  64
#define HEADDIM 64
#define D_CONV  4
#define BATCH   2
#define SEQLEN  4096
#define BL (BATCH * SEQLEN)      // 8192

// ---------------- scratch (device globals; no allocation allowed) ----------
__device__ float g_proj[(size_t)BL * INNER];            // in_proj output (fp32)
__device__ float g_gate[(size_t)BL * INNER];            // sigmoid(gate_proj)
__device__ float g_x[(size_t)BL * INNER];               // conv+silu output X
__device__ float g_dt[(size_t)BL * NHEADS];             // softplus(dt)

__device__ __half g_ah[(size_t)BL * D_MODEL];           // hidden hi
__device__ __half g_al[(size_t)BL * D_MODEL];           // hidden lo
__device__ __half g_iw[(size_t)INNER * D_MODEL];        // in_w fp16
__device__ __half g_gw[(size_t)INNER * D_MODEL];        // gate_w fp16
__device__ __half g_ow[(size_t)D_MODEL * INNER];        // out_w fp16
__device__ __half g_ch[(size_t)BL * INNER];             // comb hi
__device__ __half g_cl[(size_t)BL * INNER];             // comb lo

// ===================== PTX helpers ==========================================
__device__ __forceinline__ uint32_t smem_to_u32(const void* smem_ptr) {
    uint32_t addr;
    asm("{ .reg .u64 tmp; cvta.to.shared.u64 tmp, %1; cvt.u32.u64 %0, tmp; }"
        : "=r"(addr) : "l"(smem_ptr));
    return addr;
}

#define MBARRIER_INIT(mbar, count) \
    asm volatile("mbarrier.init.shared.b64 [%0], %1;" \
        :: "r"((uint32_t)(mbar)), "r"((uint32_t)(count)) : "memory")

#define MBARRIER_EXPECT_TX(mbar, bytes) \
    asm volatile("mbarrier.arrive.expect_tx.shared.b64 _, [%0], %1;" \
        :: "r"((uint32_t)(mbar)), "r"((uint32_t)(bytes)) : "memory")

#define MBARRIER_WAIT_PARITY(mbar, parity) do { \
    uint32_t _m = (uint32_t)(mbar); uint32_t _p = (uint32_t)(parity); uint32_t _d; \
    asm volatile( \
        "{\n\t.reg .pred p;\n\t" \
        "mbarrier.try_wait.parity.acquire.cta.shared::cta.b64 p, [%1], %2;\n\t" \
        "selp.b32 %0, 1, 0, p;\n\t}" \
        : "=r"(_d) : "r"(_m), "r"(_p) : "memory"); \
    if (!_d) { \
        asm volatile( \
            "{\n\t.reg .pred P1;\n\t" \
            "WAIT_LOOP_%=:\n\t" \
            "mbarrier.try_wait.parity.acquire.cta.shared::cta.b64 P1, [%0], %1, 0x989680;\n\t" \
            "@P1 bra.uni WAIT_DONE_%=;\n\t" \
            "bra.uni WAIT_LOOP_%=;\n\t" \
            "WAIT_DONE_%=:\n\t}" \
            :: "r"(_m), "r"(_p) : "memory"); \
    } \
} while (0)

#define TMA2D(smemaddr, tmapptr, cx, cy, mbar) \
    asm volatile( \
        "cp.async.bulk.tensor.2d.shared::cta.global.tile.mbarrier::complete_tx::bytes " \
        "[%0], [%1, {%2, %3}], [%4];" \
        :: "r"((uint32_t)(smemaddr)), "l"(tmapptr), "r"((int)(cx)), "r"((int)(cy)), \
           "r"((uint32_t)(mbar)) : "memory")

__device__ __forceinline__ void ldsm_x4(uint32_t* r, uint32_t addr) {
    asm volatile("ldmatrix.sync.aligned.m8n8.x4.shared.b16 {%0,%1,%2,%3}, [%4];"
        : "=r"(r[0]), "=r"(r[1]), "=r"(r[2]), "=r"(r[3]) : "r"(addr));
}

__device__ __forceinline__ void mma16816(float* d, const uint32_t* a, const uint32_t* b) {
    asm volatile(
        "mma.sync.aligned.m16n8k16.row.col.f32.f16.f16.f32 "
        "{%0,%1,%2,%3}, {%4,%5,%6,%7}, {%8,%9}, {%0,%1,%2,%3};"
        : "+f"(d[0]), "+f"(d[1]), "+f"(d[2]), "+f"(d[3])
        : "r"(a[0]), "r"(a[1]), "r"(a[2]), "r"(a[3]), "r"(b[0]), "r"(b[1]));
}

#define SWZ(o) ((o) ^ (((o) >> 3) & 0x70))

// ===================== HMMA GEMM =============================================
// C[M,Ntotal] = (Ah+Al)[M,K] * B[N,K]^T, fp16 2-term split on A, fp32 acc.
// Tile 128(M) x 256(N), KC=64, 3-stage TMA pipeline, 8 warps (2x4), warp 64x64.
#define TILE_M 128
#define TILE_N 256
#define KC 64
#define SOFF_AH 0
#define SOFF_AL 16384
#define SOFF_B  32768
#define STAGE_BYTES 65536
#define NSTAGE 3
#define GEMM_SMEM (1024 + NSTAGE * STAGE_BYTES)

__global__ __launch_bounds__(256, 1)
void hmma_gemm(const __grid_constant__ CUtensorMap tAh,
               const __grid_constant__ CUtensorMap tAl,
               const __grid_constant__ CUtensorMap tB,
               float* __restrict__ C, int Ntotal, int K, int epi)
{
    extern __shared__ __align__(1024) char smem[];
    const uint32_t sb = smem_to_u32(smem);
    const uint32_t sdata = sb + 1024;
    const int tid = threadIdx.x;
    const int wid = tid >> 5;
    const int lane = tid & 31;
    const int wm = wid >> 2;          // 0..1   (64 rows each)
    const int wn = wid & 3;           // 0..3   (64 cols each)
    const int bm = blockIdx.y * TILE_M;
    const int bn = blockIdx.x * TILE_N;

    uint32_t full[NSTAGE];
#pragma unroll
    for (int s = 0; s < NSTAGE; s++) full[s] = sb + 64 + s * 16;

    if (tid == 0) {
#pragma unroll
        for (int s = 0; s < NSTAGE; s++) MBARRIER_INIT(full[s], 1);
    }
    __syncthreads();

    const int NC = K / KC;

    if (tid == 0) {
#pragma unroll
        for (int s = 0; s < NSTAGE; s++) {
            if (s < NC) {
                uint32_t st = sdata + s * STAGE_BYTES;
                MBARRIER_EXPECT_TX(full[s], STAGE_BYTES);
                TMA2D(st + SOFF_AH, &tAh, s * KC, bm, full[s]);
                TMA2D(st + SOFF_AL, &tAl, s * KC, bm, full[s]);
                TMA2D(st + SOFF_B,  &tB,  s * KC, bn, full[s]);
            }
        }
    }

    // per-thread ldmatrix base offsets (within a stage tile, before k-step add)
    uint32_t abase[4], bbase[4];
#pragma unroll
    for (int mt = 0; mt < 4; mt++) {
        int row = wm * 64 + mt * 16 + (lane & 15);
        abase[mt] = (uint32_t)(row * 128 + ((lane >> 4) * 16));
    }
#pragma unroll
    for (int q = 0; q < 4; q++) {
        int row = wn * 64 + q * 16 + ((lane >> 4) << 3) + (lane & 7);
        bbase[q] = (uint32_t)(row * 128 + (((lane >> 3) & 1) * 16));
    }

    float acc[4][8][4];
#pragma unroll
    for (int mt = 0; mt < 4; mt++)
#pragma unroll
        for (int nt = 0; nt < 8; nt++)
#pragma unroll
            for (int k = 0; k < 4; k++) acc[mt][nt][k] = 0.f;

    int ph[NSTAGE];
#pragma unroll
    for (int s = 0; s < NSTAGE; s++) ph[s] = 0;

    for (int c = 0; c < NC; c++) {
        const int s = c % NSTAGE;
        const uint32_t st = sdata + s * STAGE_BYTES;
        MBARRIER_WAIT_PARITY(full[s], ph[s]);
        ph[s] ^= 1;

#pragma unroll
        for (int ks = 0; ks < 4; ks++) {
            const uint32_t kb = ks * 32;
            uint32_t ah[4][4], al[4][4], bf[4][4];
#pragma unroll
            for (int mt = 0; mt < 4; mt++) {
                uint32_t off = SWZ(abase[mt] + kb);
                ldsm_x4(ah[mt], st + SOFF_AH + off);
                ldsm_x4(al[mt], st + SOFF_AL + off);
            }
#pragma unroll
            for (int q = 0; q < 4; q++) {
                uint32_t off = SWZ(bbase[q] + kb);
                ldsm_x4(bf[q], st + SOFF_B + off);
            }
#pragma unroll
            for (int mt = 0; mt < 4; mt++) {
#pragma unroll
                for (int nt = 0; nt < 8; nt++) {
                    const uint32_t* Bf = &bf[nt >> 1][(nt & 1) * 2];
                    mma16816(acc[mt][nt], ah[mt], Bf);
                    mma16816(acc[mt][nt], al[mt], Bf);
                }
            }
        }
        __syncthreads();   // all reads of stage s done
        if (tid == 0 && c + NSTAGE < NC) {
            MBARRIER_EXPECT_TX(full[s], STAGE_BYTES);
            TMA2D(st + SOFF_AH, &tAh, (c + NSTAGE) * KC, bm, full[s]);
            TMA2D(st + SOFF_AL, &tAl, (c + NSTAGE) * KC, bm, full[s]);
            TMA2D(st + SOFF_B,  &tB,  (c + NSTAGE) * KC, bn, full[s]);
        }
    }

    // epilogue: each quad's float2 pairs form full 32B sectors
    const int g = lane >> 2;
    const int nq = (lane & 3) * 2;
#pragma unroll
    for (int mt = 0; mt < 4; mt++) {
        int r0 = bm + wm * 64 + mt * 16 + g;
#pragma unroll
        for (int nt = 0; nt < 8; nt++) {
            int cc = bn + wn * 64 + nt * 8 + nq;
            float2 v0 = make_float2(acc[mt][nt][0], acc[mt][nt][1]);
            float2 v1 = make_float2(acc[mt][nt][2], acc[mt][nt][3]);
            if (epi == 1) {
                v0.x = 1.f / (1.f + expf(-v0.x));
                v0.y = 1.f / (1.f + expf(-v0.y));
                v1.x = 1.f / (1.f + expf(-v1.x));
                v1.y = 1.f / (1.f + expf(-v1.y));
            }
            *reinterpret_cast<float2*>(C + (size_t)r0 * Ntotal + cc) = v0;
            *reinterpret_cast<float2*>(C + (size_t)(r0 + 8) * Ntotal + cc) = v1;
        }
    }
}

// ===================== fp32 -> fp16 hi/lo split ==============================
__global__ __launch_bounds__(256)
void split_hi_lo(const float* __restrict__ x, __half* __restrict__ hi,
                 __half* __restrict__ lo, int n)
{
    int i = (blockIdx.x * 256 + threadIdx.x) * 4;
    if (i >= n) return;
    float4 v = *reinterpret_cast<const float4*>(x + i);
    __half h0 = __float2half_rn(v.x);
    __half h1 = __float2half_rn(v.y);
    __half h2 = __float2half_rn(v.z);
    __half h3 = __float2half_rn(v.w);
    __half l0 = __float2half_rn(v.x - __half2float(h0));
    __half l1 = __float2half_rn(v.y - __half2float(h1));
    __half l2 = __float2half_rn(v.z - __half2float(h2));
    __half l3 = __float2half_rn(v.w - __half2float(h3));
    *reinterpret_cast<__half2*>(hi + i)     = __halves2half2(h0, h1);
    *reinterpret_cast<__half2*>(hi + i + 2) = __halves2half2(h2, h3);
    *reinterpret_cast<__half2*>(lo + i)     = __halves2half2(l0, l1);
    *reinterpret_cast<__half2*>(lo + i + 2) = __halves2half2(l2, l3);
}

// ===================== fp32 -> fp16 plain convert ============================
__global__ __launch_bounds__(256)
void cvt_f16(const float* __restrict__ x, __half* __restrict__ y, int n)
{
    int i = (blockIdx.x * 256 + threadIdx.x) * 4;
    if (i >= n) return;
    float4 v = *reinterpret_cast<const float4*>(x + i);
    *reinterpret_cast<__half2*>(y + i)     = __halves2half2(__float2half_rn(v.x), __float2half_rn(v.y));
    *reinterpret_cast<__half2*>(y + i + 2) = __halves2half2(__float2half_rn(v.z), __float2half_rn(v.w));
}

// ---------------- conv(K=4, causal, depthwise) + SiLU + dt(softplus) -------
__global__ __launch_bounds__(256)
void conv_dt_kernel(const float* __restrict__ proj,
                    const float* __restrict__ cw,
                    const float* __restrict__ cb,
                    const float* __restrict__ dtw,
                    const float* __restrict__ dtb,
                    float* __restrict__ Xout,
                    float* __restrict__ dt_out)
{
    const int bl = blockIdx.x;
    const int l = bl % SEQLEN;
    __shared__ float sx[INNER];
    __shared__ float spart[NHEADS][4];

    const int tid = threadIdx.x;
    const float* base = proj + (size_t)bl * INNER;

    for (int c = tid; c < INNER; c += 256) {
        float accv = cb[c];
#pragma unroll
        for (int k = 0; k < D_CONV; k++) {
            int ll = l + k - (D_CONV - 1);
            float xv = (ll >= 0) ? base[(ptrdiff_t)(k - (D_CONV - 1)) * INNER + c] : 0.f;
            accv = fmaf(cw[c * D_CONV + k], xv, accv);
        }
        float s = accv / (1.f + expf(-accv));
        sx[c] = s;
        Xout[(size_t)bl * INNER + c] = s;
    }
    __syncthreads();

    {
        int h = tid >> 2;
        int part = tid & 3;
        float sum = 0.f;
        int p0 = part * 16;
#pragma unroll
        for (int p = 0; p < 16; p++)
            sum = fmaf(sx[h * HEADDIM + p0 + p], dtw[h * HEADDIM + p0 + p], sum);
        spart[h][part] = sum;
    }
    __syncthreads();
    if (tid < NHEADS) {
        float v = spart[tid][0] + spart[tid][1] + spart[tid][2] + spart[tid][3] + dtb[tid];
        float sp = (v > 20.f) ? v : log1pf(expf(v));
        dt_out[(size_t)bl * NHEADS + tid] = sp;
    }
}

// ---------------- SSM scan + output fusion (emits fp16 hi/lo) ---------------
#define NSEG 16
#define SEG (SEQLEN / NSEG)     // 256

__global__ __launch_bounds__(1024, 1)
void scan_kernel(const float* __restrict__ X,
                 const float* __restrict__ dt,
                 const float* __restrict__ gate,
                 const float* __restrict__ A_log,
                 const float* __restrict__ Bv,
                 const float* __restrict__ Cv,
                 const float* __restrict__ Dv,
                 __half* __restrict__ ch,
                 __half* __restrict__ cl)
{
    const int bh = blockIdx.x;
    const int h = bh % NHEADS;
    const int b = bh / NHEADS;
    const int p = threadIdx.x;
    const int s = threadIdx.y;

    const int hp = h * HEADDIM + p;
    const float acoef = -expf(A_log[hp]);
    const float Bc = Bv[hp];
    const float Cc = Cv[hp];
    const float Dc = Dv[hp];

    const size_t baseX = (size_t)b * SEQLEN * INNER + (size_t)h * HEADDIM + p;
    const size_t baseDt = (size_t)b * SEQLEN * NHEADS + h;
    const int l0 = s * SEG;

    __shared__ float agg_a[NSEG][HEADDIM];
    __shared__ float agg_u[NSEG][HEADDIM];
    __shared__ float pre[NSEG][HEADDIM];

    float ap = 1.f, ss = 0.f;
    for (int i = 0; i < SEG; i++) {
        int l = l0 + i;
        float d = dt[baseDt + (size_t)l * NHEADS];
        float xv = X[baseX + (size_t)l * INNER];
        float a = expf(d * acoef);
        float u = d * Bc * xv;
        ap *= a;
        ss = fmaf(a, ss, u);
    }
    agg_a[s][p] = ap;
    agg_u[s][p] = ss;
    __syncthreads();

    if (s == 0) {
        float st = 0.f;
#pragma unroll
        for (int j = 0; j < NSEG; j++) {
            pre[j][p] = st;
            st = fmaf(agg_a[j][p], st, agg_u[j][p]);
        }
    }
    __syncthreads();

    float sprev = pre[s][p];
    for (int i = 0; i < SEG; i++) {
        int l = l0 + i;
        float d = dt[baseDt + (size_t)l * NHEADS];
        size_t idx = baseX + (size_t)l * INNER;
        float xv = X[idx];
        float a = expf(d * acoef);
        float u = d * Bc * xv;
        sprev = fmaf(a, sprev, u);
        float y = fmaf(Cc, sprev, Dc * xv) * gate[idx];
        __half hpart = __float2half_rn(y);
        ch[idx] = hpart;
        cl[idx] = __float2half_rn(y - __half2float(hpart));
    }
}

// ===================== host side ============================================
typedef CUresult (*TmEncodeFn)(CUtensorMap*, CUtensorMapDataType, cuuint32_t,
                               void*, const cuuint64_t*, const cuuint64_t*,
                               const cuuint32_t*, const cuuint32_t*,
                               CUtensorMapInterleave, CUtensorMapSwizzle,
                               CUtensorMapL2promotion, CUtensorMapFloatOOBfill);

static void make_tm(TmEncodeFn fn, CUtensorMap* tm, const void* ptr,
                    int rows, int K, int boxRows)
{
    cuuint64_t dims[2]    = {(cuuint64_t)K, (cuuint64_t)rows};
    cuuint64_t strides[1] = {(cuuint64_t)K * 2};
    cuuint32_t box[2]     = {64u, (cuuint32_t)boxRows};
    cuuint32_t es[2]      = {1u, 1u};
    fn(tm, CU_TENSOR_MAP_DATA_TYPE_FLOAT16, 2, (void*)ptr,
       dims, strides, box, es,
       CU_TENSOR_MAP_INTERLEAVE_NONE, CU_TENSOR_MAP_SWIZZLE_128B,
       CU_TENSOR_MAP_L2_PROMOTION_L2_128B, CU_TENSOR_MAP_FLOAT_OOB_FILL_NONE);
}

extern "C" void kernel_launch(void* const* d_in, const int* in_sizes, int n_in,
                              void* d_out, int out_size)
{
    const float* hidden = (const float*)d_in[0];
    const float* in_w   = (const float*)d_in[1];
    const float* gate_w = (const float*)d_in[2];
    const float* out_w  = (const float*)d_in[3];
    const float* conv_w = (const float*)d_in[4];
    const float* conv_b = (const float*)d_in[5];
    const float* dt_w   = (const float*)d_in[6];
    const float* dt_b   = (const float*)d_in[7];
    const float* A_log  = (const float*)d_in[8];
    const float* Bv     = (const float*)d_in[9];
    const float* Cv     = (const float*)d_in[10];
    const float* Dv     = (const float*)d_in[11];
    float* out          = (float*)d_out;

    float *proj, *gatebuf, *xbuf, *dtbuf;
    __half *ah, *al, *iw, *gw, *ow, *ch, *cl;
    cudaGetSymbolAddress((void**)&proj,    g_proj);
    cudaGetSymbolAddress((void**)&gatebuf, g_gate);
    cudaGetSymbolAddress((void**)&xbuf,    g_x);
    cudaGetSymbolAddress((void**)&dtbuf,   g_dt);
    cudaGetSymbolAddress((void**)&ah, g_ah);
    cudaGetSymbolAddress((void**)&al, g_al);
    cudaGetSymbolAddress((void**)&iw, g_iw);
    cudaGetSymbolAddress((void**)&gw, g_gw);
    cudaGetSymbolAddress((void**)&ow, g_ow);
    cudaGetSymbolAddress((void**)&ch, g_ch);
    cudaGetSymbolAddress((void**)&cl, g_cl);

    TmEncodeFn enc = nullptr;
    {
        void* p = nullptr;
        cudaDriverEntryPointQueryResult qr;
        cudaGetDriverEntryPointByVersion("cuTensorMapEncodeTiled", &p, 12000,
                                         cudaEnableDefault, &qr);
        enc = (TmEncodeFn)p;
    }

    // splits / converts
    {
        int n;
        n = BL * D_MODEL;        split_hi_lo<<<n / 1024, 256>>>(hidden, ah, al, n);
        n = INNER * D_MODEL;     cvt_f16<<<n / 1024, 256>>>(in_w,   iw, n);
        n = INNER * D_MODEL;     cvt_f16<<<n / 1024, 256>>>(gate_w, gw, n);
        n = D_MODEL * INNER;     cvt_f16<<<n / 1024, 256>>>(out_w,  ow, n);
    }

    CUtensorMap tm_ah, tm_al, tm_iw, tm_gw, tm_ow, tm_ch, tm_cl;
    make_tm(enc, &tm_ah, ah, BL,      D_MODEL, 128);
    make_tm(enc, &tm_al, al, BL,      D_MODEL, 128);
    make_tm(enc, &tm_iw, iw, INNER,   D_MODEL, 256);
    make_tm(enc, &tm_gw, gw, INNER,   D_MODEL, 256);
    make_tm(enc, &tm_ow, ow, D_MODEL, INNER,   256);
    make_tm(enc, &tm_ch, ch, BL,      INNER,   128);
    make_tm(enc, &tm_cl, cl, BL,      INNER,   128);

    cudaFuncSetAttribute(hmma_gemm, cudaFuncAttributeMaxDynamicSharedMemorySize, GEMM_SMEM);

    // 1) in_proj: (8192 x 2048) @ (4096 x 2048)^T -> proj
    {
        dim3 grid(INNER / TILE_N, BL / TILE_M);
        hmma_gemm<<<grid, 256, GEMM_SMEM>>>(tm_ah, tm_al, tm_iw,
                                            proj, INNER, D_MODEL, 0);
    }
    // 2) gate: same shapes, sigmoid epilogue
    {
        dim3 grid(INNER / TILE_N, BL / TILE_M);
        hmma_gemm<<<grid, 256, GEMM_SMEM>>>(tm_ah, tm_al, tm_gw,
                                            gatebuf, INNER, D_MODEL, 1);
    }
    // 3) conv + silu + dt
    conv_dt_kernel<<<BL, 256>>>(proj, conv_w, conv_b, dt_w, dt_b, xbuf, dtbuf);
    // 4) SSM scan fused with y, gate, and fp16 split
    {
        dim3 blk(HEADDIM, NSEG);
        scan_kernel<<<BATCH * NHEADS, blk>>>(xbuf, dtbuf, gatebuf, A_log, Bv, Cv, Dv, ch, cl);
    }
    // 5) out_proj: (8192 x 4096) @ (2048 x 4096)^T -> out
    {
        dim3 grid(D_MODEL / TILE_N, BL / TILE_M);
        hmma_gemm<<<grid, 256, GEMM_SMEM>>>(tm_ch, tm_cl, tm_ow,
                                            out, D_MODEL, INNER, 0);
    }
}

// round 5
// speedup vs baseline: 5.2471x; 1.1325x over previous
#include <cuda.h>
#include <cuda_runtime.h>
#include <cuda_fp16.h>
#include <math.h>

#define D_MODEL 2048
#define INNER   4096
#define NHEADS  64
#define HEADDIM 64
#define D_CONV  4
#define BATCH   2
#define SEQLEN  4096
#define BL (BATCH * SEQLEN)      // 8192

// ---------------- scratch (device globals; no allocation allowed) ----------
__device__ float g_proj[(size_t)BL * INNER];            // in_proj output (fp32)
__device__ float g_gate[(size_t)BL * INNER];            // sigmoid(gate_proj)
__device__ float g_x[(size_t)BL * INNER];               // conv+silu output X
__device__ float g_dt[(size_t)BL * NHEADS];             // softplus(dt)

__device__ __half g_ah[(size_t)BL * D_MODEL];           // hidden hi
__device__ __half g_al[(size_t)BL * D_MODEL];           // hidden lo
__device__ __half g_iw[(size_t)INNER * D_MODEL];        // in_w fp16
__device__ __half g_gw[(size_t)INNER * D_MODEL];        // gate_w fp16
__device__ __half g_ow[(size_t)D_MODEL * INNER];        // out_w fp16
__device__ __half g_ch[(size_t)BL * INNER];             // comb hi
__device__ __half g_cl[(size_t)BL * INNER];             // comb lo

// ===================== PTX helpers ==========================================
__device__ __forceinline__ uint32_t smem_to_u32(const void* smem_ptr) {
    uint32_t addr;
    asm("{ .reg .u64 tmp; cvta.to.shared.u64 tmp, %1; cvt.u32.u64 %0, tmp; }"
        : "=r"(addr) : "l"(smem_ptr));
    return addr;
}

#define MBARRIER_INIT(mbar, count) \
    asm volatile("mbarrier.init.shared.b64 [%0], %1;" \
        :: "r"((uint32_t)(mbar)), "r"((uint32_t)(count)) : "memory")

#define MBARRIER_EXPECT_TX(mbar, bytes) \
    asm volatile("mbarrier.arrive.expect_tx.shared.b64 _, [%0], %1;" \
        :: "r"((uint32_t)(mbar)), "r"((uint32_t)(bytes)) : "memory")

#define MBARRIER_WAIT_PARITY(mbar, parity) do { \
    uint32_t _m = (uint32_t)(mbar); uint32_t _p = (uint32_t)(parity); uint32_t _d; \
    asm volatile( \
        "{\n\t.reg .pred p;\n\t" \
        "mbarrier.try_wait.parity.acquire.cta.shared::cta.b64 p, [%1], %2;\n\t" \
        "selp.b32 %0, 1, 0, p;\n\t}" \
        : "=r"(_d) : "r"(_m), "r"(_p) : "memory"); \
    if (!_d) { \
        asm volatile( \
            "{\n\t.reg .pred P1;\n\t" \
            "WAIT_LOOP_%=:\n\t" \
            "mbarrier.try_wait.parity.acquire.cta.shared::cta.b64 P1, [%0], %1, 0x989680;\n\t" \
            "@P1 bra.uni WAIT_DONE_%=;\n\t" \
            "bra.uni WAIT_LOOP_%=;\n\t" \
            "WAIT_DONE_%=:\n\t}" \
            :: "r"(_m), "r"(_p) : "memory"); \
    } \
} while (0)

#define TMA2D(smemaddr, tmapptr, cx, cy, mbar) \
    asm volatile( \
        "cp.async.bulk.tensor.2d.shared::cta.global.tile.mbarrier::complete_tx::bytes " \
        "[%0], [%1, {%2, %3}], [%4];" \
        :: "r"((uint32_t)(smemaddr)), "l"(tmapptr), "r"((int)(cx)), "r"((int)(cy)), \
           "r"((uint32_t)(mbar)) : "memory")

__device__ __forceinline__ void ldsm_x4(uint32_t* r, uint32_t addr) {
    asm volatile("ldmatrix.sync.aligned.m8n8.x4.shared.b16 {%0,%1,%2,%3}, [%4];"
        : "=r"(r[0]), "=r"(r[1]), "=r"(r[2]), "=r"(r[3]) : "r"(addr));
}

__device__ __forceinline__ void mma16816(float* d, const uint32_t* a, const uint32_t* b) {
    asm volatile(
        "mma.sync.aligned.m16n8k16.row.col.f32.f16.f16.f32 "
        "{%0,%1,%2,%3}, {%4,%5,%6,%7}, {%8,%9}, {%0,%1,%2,%3};"
        : "+f"(d[0]), "+f"(d[1]), "+f"(d[2]), "+f"(d[3])
        : "r"(a[0]), "r"(a[1]), "r"(a[2]), "r"(a[3]), "r"(b[0]), "r"(b[1]));
}

#define SWZ(o) ((o) ^ (((o) >> 3) & 0x70))

// ===================== HMMA GEMM =============================================
// C[M,Ntotal] = A[M,K] * B[N,K]^T, fp32 acc.
// SPLIT=true : A = Ah + Al (fp16 2-term), 3-stage (64KB/stage)
// SPLIT=false: A = Ah only,               4-stage (48KB/stage)
// Tile 128(M) x 256(N), KC=64, 8 warps (2x4), warp tile 64x64.
#define TILE_M 128
#define TILE_N 256
#define KC 64

template<bool SPLIT, int NST>
__global__ __launch_bounds__(256, 1)
void hmma_gemm(const __grid_constant__ CUtensorMap tAh,
               const __grid_constant__ CUtensorMap tAl,
               const __grid_constant__ CUtensorMap tB,
               float* __restrict__ C, int Ntotal, int K, int epi)
{
    constexpr uint32_t SOFF_AH = 0;
    constexpr uint32_t SOFF_AL = 16384;                 // only used if SPLIT
    constexpr uint32_t SOFF_B  = SPLIT ? 32768 : 16384;
    constexpr uint32_t STAGE   = SPLIT ? 65536 : 49152;

    extern __shared__ __align__(1024) char smem[];
    const uint32_t sb = smem_to_u32(smem);
    const uint32_t sdata = sb + 1024;
    const int tid = threadIdx.x;
    const int wid = tid >> 5;
    const int lane = tid & 31;
    const int wm = wid >> 2;          // 0..1   (64 rows each)
    const int wn = wid & 3;           // 0..3   (64 cols each)
    const int bm = blockIdx.y * TILE_M;
    const int bn = blockIdx.x * TILE_N;

    uint32_t full[NST];
#pragma unroll
    for (int s = 0; s < NST; s++) full[s] = sb + 64 + s * 16;

    if (tid == 0) {
#pragma unroll
        for (int s = 0; s < NST; s++) MBARRIER_INIT(full[s], 1);
    }
    __syncthreads();

    const int NC = K / KC;

    if (tid == 0) {
#pragma unroll
        for (int s = 0; s < NST; s++) {
            if (s < NC) {
                uint32_t st = sdata + s * STAGE;
                MBARRIER_EXPECT_TX(full[s], STAGE);
                TMA2D(st + SOFF_AH, &tAh, s * KC, bm, full[s]);
                if (SPLIT) TMA2D(st + SOFF_AL, &tAl, s * KC, bm, full[s]);
                TMA2D(st + SOFF_B,  &tB,  s * KC, bn, full[s]);
            }
        }
    }

    uint32_t abase[4], bbase[4];
#pragma unroll
    for (int mt = 0; mt < 4; mt++) {
        int row = wm * 64 + mt * 16 + (lane & 15);
        abase[mt] = (uint32_t)(row * 128 + ((lane >> 4) * 16));
    }
#pragma unroll
    for (int q = 0; q < 4; q++) {
        int row = wn * 64 + q * 16 + ((lane >> 4) << 3) + (lane & 7);
        bbase[q] = (uint32_t)(row * 128 + (((lane >> 3) & 1) * 16));
    }

    float acc[4][8][4];
#pragma unroll
    for (int mt = 0; mt < 4; mt++)
#pragma unroll
        for (int nt = 0; nt < 8; nt++)
#pragma unroll
            for (int k = 0; k < 4; k++) acc[mt][nt][k] = 0.f;

    int ph[NST];
#pragma unroll
    for (int s = 0; s < NST; s++) ph[s] = 0;

    for (int c = 0; c < NC; c++) {
        const int s = c % NST;
        const uint32_t st = sdata + s * STAGE;
        MBARRIER_WAIT_PARITY(full[s], ph[s]);
        ph[s] ^= 1;

#pragma unroll
        for (int ks = 0; ks < 4; ks++) {
            const uint32_t kb = ks * 32;
            uint32_t ah[4][4], al[4][4], bf[4][4];
#pragma unroll
            for (int mt = 0; mt < 4; mt++) {
                uint32_t off = SWZ(abase[mt] + kb);
                ldsm_x4(ah[mt], st + SOFF_AH + off);
                if (SPLIT) ldsm_x4(al[mt], st + SOFF_AL + off);
            }
#pragma unroll
            for (int q = 0; q < 4; q++) {
                uint32_t off = SWZ(bbase[q] + kb);
                ldsm_x4(bf[q], st + SOFF_B + off);
            }
#pragma unroll
            for (int mt = 0; mt < 4; mt++) {
#pragma unroll
                for (int nt = 0; nt < 8; nt++) {
                    const uint32_t* Bf = &bf[nt >> 1][(nt & 1) * 2];
                    mma16816(acc[mt][nt], ah[mt], Bf);
                    if (SPLIT) mma16816(acc[mt][nt], al[mt], Bf);
                }
            }
        }
        __syncthreads();   // all reads of stage s done
        if (tid == 0 && c + NST < NC) {
            MBARRIER_EXPECT_TX(full[s], STAGE);
            TMA2D(st + SOFF_AH, &tAh, (c + NST) * KC, bm, full[s]);
            if (SPLIT) TMA2D(st + SOFF_AL, &tAl, (c + NST) * KC, bm, full[s]);
            TMA2D(st + SOFF_B,  &tB,  (c + NST) * KC, bn, full[s]);
        }
    }

    // epilogue
    const int g = lane >> 2;
    const int nq = (lane & 3) * 2;
#pragma unroll
    for (int mt = 0; mt < 4; mt++) {
        int r0 = bm + wm * 64 + mt * 16 + g;
#pragma unroll
        for (int nt = 0; nt < 8; nt++) {
            int cc = bn + wn * 64 + nt * 8 + nq;
            float2 v0 = make_float2(acc[mt][nt][0], acc[mt][nt][1]);
            float2 v1 = make_float2(acc[mt][nt][2], acc[mt][nt][3]);
            if (epi == 1) {
                v0.x = 1.f / (1.f + expf(-v0.x));
                v0.y = 1.f / (1.f + expf(-v0.y));
                v1.x = 1.f / (1.f + expf(-v1.x));
                v1.y = 1.f / (1.f + expf(-v1.y));
            }
            *reinterpret_cast<float2*>(C + (size_t)r0 * Ntotal + cc) = v0;
            *reinterpret_cast<float2*>(C + (size_t)(r0 + 8) * Ntotal + cc) = v1;
        }
    }
}

// ===================== fp32 -> fp16 hi/lo split ==============================
__global__ __launch_bounds__(256)
void split_hi_lo(const float* __restrict__ x, __half* __restrict__ hi,
                 __half* __restrict__ lo, int n)
{
    int i = (blockIdx.x * 256 + threadIdx.x) * 4;
    if (i >= n) return;
    float4 v = *reinterpret_cast<const float4*>(x + i);
    __half h0 = __float2half_rn(v.x);
    __half h1 = __float2half_rn(v.y);
    __half h2 = __float2half_rn(v.z);
    __half h3 = __float2half_rn(v.w);
    __half l0 = __float2half_rn(v.x - __half2float(h0));
    __half l1 = __float2half_rn(v.y - __half2float(h1));
    __half l2 = __float2half_rn(v.z - __half2float(h2));
    __half l3 = __float2half_rn(v.w - __half2float(h3));
    *reinterpret_cast<__half2*>(hi + i)     = __halves2half2(h0, h1);
    *reinterpret_cast<__half2*>(hi + i + 2) = __halves2half2(h2, h3);
    *reinterpret_cast<__half2*>(lo + i)     = __halves2half2(l0, l1);
    *reinterpret_cast<__half2*>(lo + i + 2) = __halves2half2(l2, l3);
}

// ===================== fp32 -> fp16 plain convert ============================
__global__ __launch_bounds__(256)
void cvt_f16(const float* __restrict__ x, __half* __restrict__ y, int n)
{
    int i = (blockIdx.x * 256 + threadIdx.x) * 4;
    if (i >= n) return;
    float4 v = *reinterpret_cast<const float4*>(x + i);
    *reinterpret_cast<__half2*>(y + i)     = __halves2half2(__float2half_rn(v.x), __float2half_rn(v.y));
    *reinterpret_cast<__half2*>(y + i + 2) = __halves2half2(__float2half_rn(v.z), __float2half_rn(v.w));
}

// ---------------- conv(K=4, causal, depthwise) + SiLU + dt(softplus) -------
__global__ __launch_bounds__(256)
void conv_dt_kernel(const float* __restrict__ proj,
                    const float* __restrict__ cw,
                    const float* __restrict__ cb,
                    const float* __restrict__ dtw,
                    const float* __restrict__ dtb,
                    float* __restrict__ Xout,
                    float* __restrict__ dt_out)
{
    const int bl = blockIdx.x;
    const int l = bl % SEQLEN;
    __shared__ float sx[INNER];
    __shared__ float spart[NHEADS][4];

    const int tid = threadIdx.x;
    const float* base = proj + (size_t)bl * INNER;

    for (int c = tid; c < INNER; c += 256) {
        float accv = cb[c];
#pragma unroll
        for (int k = 0; k < D_CONV; k++) {
            int ll = l + k - (D_CONV - 1);
            float xv = (ll >= 0) ? base[(ptrdiff_t)(k - (D_CONV - 1)) * INNER + c] : 0.f;
            accv = fmaf(cw[c * D_CONV + k], xv, accv);
        }
        float s = accv / (1.f + expf(-accv));
        sx[c] = s;
        Xout[(size_t)bl * INNER + c] = s;
    }
    __syncthreads();

    {
        int h = tid >> 2;
        int part = tid & 3;
        float sum = 0.f;
        int p0 = part * 16;
#pragma unroll
        for (int p = 0; p < 16; p++)
            sum = fmaf(sx[h * HEADDIM + p0 + p], dtw[h * HEADDIM + p0 + p], sum);
        spart[h][part] = sum;
    }
    __syncthreads();
    if (tid < NHEADS) {
        float v = spart[tid][0] + spart[tid][1] + spart[tid][2] + spart[tid][3] + dtb[tid];
        float sp = (v > 20.f) ? v : log1pf(expf(v));
        dt_out[(size_t)bl * NHEADS + tid] = sp;
    }
}

// ---------------- SSM scan + output fusion (emits fp16 hi/lo) ---------------
#define NSEG 16
#define SEG (SEQLEN / NSEG)     // 256

__global__ __launch_bounds__(1024, 1)
void scan_kernel(const float* __restrict__ X,
                 const float* __restrict__ dt,
                 const float* __restrict__ gate,
                 const float* __restrict__ A_log,
                 const float* __restrict__ Bv,
                 const float* __restrict__ Cv,
                 const float* __restrict__ Dv,
                 __half* __restrict__ ch,
                 __half* __restrict__ cl)
{
    const int bh = blockIdx.x;
    const int h = bh % NHEADS;
    const int b = bh / NHEADS;
    const int p = threadIdx.x;
    const int s = threadIdx.y;

    const int hp = h * HEADDIM + p;
    const float acoef = -expf(A_log[hp]);
    const float Bc = Bv[hp];
    const float Cc = Cv[hp];
    const float Dc = Dv[hp];

    const size_t baseX = (size_t)b * SEQLEN * INNER + (size_t)h * HEADDIM + p;
    const size_t baseDt = (size_t)b * SEQLEN * NHEADS + h;
    const int l0 = s * SEG;

    __shared__ float agg_a[NSEG][HEADDIM];
    __shared__ float agg_u[NSEG][HEADDIM];
    __shared__ float pre[NSEG][HEADDIM];

    float ap = 1.f, ss = 0.f;
    for (int i = 0; i < SEG; i++) {
        int l = l0 + i;
        float d = dt[baseDt + (size_t)l * NHEADS];
        float xv = X[baseX + (size_t)l * INNER];
        float a = expf(d * acoef);
        float u = d * Bc * xv;
        ap *= a;
        ss = fmaf(a, ss, u);
    }
    agg_a[s][p] = ap;
    agg_u[s][p] = ss;
    __syncthreads();

    if (s == 0) {
        float st = 0.f;
#pragma unroll
        for (int j = 0; j < NSEG; j++) {
            pre[j][p] = st;
            st = fmaf(agg_a[j][p], st, agg_u[j][p]);
        }
    }
    __syncthreads();

    float sprev = pre[s][p];
    for (int i = 0; i < SEG; i++) {
        int l = l0 + i;
        float d = dt[baseDt + (size_t)l * NHEADS];
        size_t idx = baseX + (size_t)l * INNER;
        float xv = X[idx];
        float a = expf(d * acoef);
        float u = d * Bc * xv;
        sprev = fmaf(a, sprev, u);
        float y = fmaf(Cc, sprev, Dc * xv) * gate[idx];
        __half hpart = __float2half_rn(y);
        ch[idx] = hpart;
        cl[idx] = __float2half_rn(y - __half2float(hpart));
    }
}

// ===================== host side ============================================
typedef CUresult (*TmEncodeFn)(CUtensorMap*, CUtensorMapDataType, cuuint32_t,
                               void*, const cuuint64_t*, const cuuint64_t*,
                               const cuuint32_t*, const cuuint32_t*,
                               CUtensorMapInterleave, CUtensorMapSwizzle,
                               CUtensorMapL2promotion, CUtensorMapFloatOOBfill);

static void make_tm(TmEncodeFn fn, CUtensorMap* tm, const void* ptr,
                    int rows, int K, int boxRows)
{
    cuuint64_t dims[2]    = {(cuuint64_t)K, (cuuint64_t)rows};
    cuuint64_t strides[1] = {(cuuint64_t)K * 2};
    cuuint32_t box[2]     = {64u, (cuuint32_t)boxRows};
    cuuint32_t es[2]      = {1u, 1u};
    fn(tm, CU_TENSOR_MAP_DATA_TYPE_FLOAT16, 2, (void*)ptr,
       dims, strides, box, es,
       CU_TENSOR_MAP_INTERLEAVE_NONE, CU_TENSOR_MAP_SWIZZLE_128B,
       CU_TENSOR_MAP_L2_PROMOTION_L2_128B, CU_TENSOR_MAP_FLOAT_OOB_FILL_NONE);
}

extern "C" void kernel_launch(void* const* d_in, const int* in_sizes, int n_in,
                              void* d_out, int out_size)
{
    const float* hidden = (const float*)d_in[0];
    const float* in_w   = (const float*)d_in[1];
    const float* gate_w = (const float*)d_in[2];
    const float* out_w  = (const float*)d_in[3];
    const float* conv_w = (const float*)d_in[4];
    const float* conv_b = (const float*)d_in[5];
    const float* dt_w   = (const float*)d_in[6];
    const float* dt_b   = (const float*)d_in[7];
    const float* A_log  = (const float*)d_in[8];
    const float* Bv     = (const float*)d_in[9];
    const float* Cv     = (const float*)d_in[10];
    const float* Dv     = (const float*)d_in[11];
    float* out          = (float*)d_out;

    float *proj, *gatebuf, *xbuf, *dtbuf;
    __half *ah, *al, *iw, *gw, *ow, *ch, *cl;
    cudaGetSymbolAddress((void**)&proj,    g_proj);
    cudaGetSymbolAddress((void**)&gatebuf, g_gate);
    cudaGetSymbolAddress((void**)&xbuf,    g_x);
    cudaGetSymbolAddress((void**)&dtbuf,   g_dt);
    cudaGetSymbolAddress((void**)&ah, g_ah);
    cudaGetSymbolAddress((void**)&al, g_al);
    cudaGetSymbolAddress((void**)&iw, g_iw);
    cudaGetSymbolAddress((void**)&gw, g_gw);
    cudaGetSymbolAddress((void**)&ow, g_ow);
    cudaGetSymbolAddress((void**)&ch, g_ch);
    cudaGetSymbolAddress((void**)&cl, g_cl);

    TmEncodeFn enc = nullptr;
    {
        void* p = nullptr;
        cudaDriverEntryPointQueryResult qr;
        cudaGetDriverEntryPointByVersion("cuTensorMapEncodeTiled", &p, 12000,
                                         cudaEnableDefault, &qr);
        enc = (TmEncodeFn)p;
    }

    // splits / converts
    {
        int n;
        n = BL * D_MODEL;        split_hi_lo<<<n / 1024, 256>>>(hidden, ah, al, n);
        n = INNER * D_MODEL;     cvt_f16<<<n / 1024, 256>>>(in_w,   iw, n);
        n = INNER * D_MODEL;     cvt_f16<<<n / 1024, 256>>>(gate_w, gw, n);
        n = D_MODEL * INNER;     cvt_f16<<<n / 1024, 256>>>(out_w,  ow, n);
    }

    CUtensorMap tm_ah, tm_al, tm_iw, tm_gw, tm_ow, tm_ch, tm_cl;
    make_tm(enc, &tm_ah, ah, BL,      D_MODEL, 128);
    make_tm(enc, &tm_al, al, BL,      D_MODEL, 128);
    make_tm(enc, &tm_iw, iw, INNER,   D_MODEL, 256);
    make_tm(enc, &tm_gw, gw, INNER,   D_MODEL, 256);
    make_tm(enc, &tm_ow, ow, D_MODEL, INNER,   256);
    make_tm(enc, &tm_ch, ch, BL,      INNER,   128);
    make_tm(enc, &tm_cl, cl, BL,      INNER,   128);

    const int SM_SPLIT   = 1024 + 3 * 65536;
    const int SM_NOSPLIT = 1024 + 4 * 49152;
    cudaFuncSetAttribute((const void*)hmma_gemm<true, 3>,
                         cudaFuncAttributeMaxDynamicSharedMemorySize, SM_SPLIT);
    cudaFuncSetAttribute((const void*)hmma_gemm<false, 4>,
                         cudaFuncAttributeMaxDynamicSharedMemorySize, SM_NOSPLIT);

    // 1) in_proj (split): (8192 x 2048) @ (4096 x 2048)^T -> proj
    {
        dim3 grid(INNER / TILE_N, BL / TILE_M);
        hmma_gemm<true, 3><<<grid, 256, SM_SPLIT>>>(tm_ah, tm_al, tm_iw,
                                                    proj, INNER, D_MODEL, 0);
    }
    // 2) gate (no split) + sigmoid epilogue
    {
        dim3 grid(INNER / TILE_N, BL / TILE_M);
        hmma_gemm<false, 4><<<grid, 256, SM_NOSPLIT>>>(tm_ah, tm_al, tm_gw,
                                                       gatebuf, INNER, D_MODEL, 1);
    }
    // 3) conv + silu + dt
    conv_dt_kernel<<<BL, 256>>>(proj, conv_w, conv_b, dt_w, dt_b, xbuf, dtbuf);
    // 4) SSM scan fused with y, gate, and fp16 split
    {
        dim3 blk(HEADDIM, NSEG);
        scan_kernel<<<BATCH * NHEADS, blk>>>(xbuf, dtbuf, gatebuf, A_log, Bv, Cv, Dv, ch, cl);
    }
    // 5) out_proj (split): (8192 x 4096) @ (2048 x 4096)^T -> out
    {
        dim3 grid(D_MODEL / TILE_N, BL / TILE_M);
        hmma_gemm<true, 3><<<grid, 256, SM_SPLIT>>>(tm_ch, tm_cl, tm_ow,
                                                    out, D_MODEL, INNER, 0);
    }
}

// round 6
// speedup vs baseline: 7.3880x; 1.4080x over previous
#include <cuda.h>
#include <cuda_runtime.h>
#include <cuda_fp16.h>
#include <math.h>

#define D_MODEL 2048
#define INNER   4096
#define NHEADS  64
#define HEADDIM 64
#define D_CONV  4
#define BATCH   2
#define SEQLEN  4096
#define BL (BATCH * SEQLEN)      // 8192

// ---------------- scratch (device globals; no allocation allowed) ----------
__device__ float g_proj[(size_t)BL * INNER];            // in_proj output (fp32)
__device__ float g_gate[(size_t)BL * INNER];            // sigmoid(gate_proj)
__device__ float g_x[(size_t)BL * INNER];               // conv+silu output X
__device__ float g_dt[(size_t)BL * NHEADS];             // softplus(dt)

__device__ __half g_hx[(size_t)BL * D_MODEL];           // hidden fp16
__device__ __half g_iw[(size_t)INNER * D_MODEL];        // in_w fp16
__device__ __half g_gw[(size_t)INNER * D_MODEL];        // gate_w fp16
__device__ __half g_ow[(size_t)D_MODEL * INNER];        // out_w fp16
__device__ __half g_cb[(size_t)BL * INNER];             // comb fp16

// ===================== PTX helpers ==========================================
__device__ __forceinline__ uint32_t smem_to_u32(const void* smem_ptr) {
    uint32_t addr;
    asm("{ .reg .u64 tmp; cvta.to.shared.u64 tmp, %1; cvt.u32.u64 %0, tmp; }"
        : "=r"(addr) : "l"(smem_ptr));
    return addr;
}

#define MBARRIER_INIT(mbar, count) \
    asm volatile("mbarrier.init.shared.b64 [%0], %1;" \
        :: "r"((uint32_t)(mbar)), "r"((uint32_t)(count)) : "memory")

#define MBARRIER_EXPECT_TX(mbar, bytes) \
    asm volatile("mbarrier.arrive.expect_tx.shared.b64 _, [%0], %1;" \
        :: "r"((uint32_t)(mbar)), "r"((uint32_t)(bytes)) : "memory")

#define MBARRIER_WAIT_PARITY(mbar, parity) do { \
    uint32_t _m = (uint32_t)(mbar); uint32_t _p = (uint32_t)(parity); uint32_t _d; \
    asm volatile( \
        "{\n\t.reg .pred p;\n\t" \
        "mbarrier.try_wait.parity.acquire.cta.shared::cta.b64 p, [%1], %2;\n\t" \
        "selp.b32 %0, 1, 0, p;\n\t}" \
        : "=r"(_d) : "r"(_m), "r"(_p) : "memory"); \
    if (!_d) { \
        asm volatile( \
            "{\n\t.reg .pred P1;\n\t" \
            "WAIT_LOOP_%=:\n\t" \
            "mbarrier.try_wait.parity.acquire.cta.shared::cta.b64 P1, [%0], %1, 0x989680;\n\t" \
            "@P1 bra.uni WAIT_DONE_%=;\n\t" \
            "bra.uni WAIT_LOOP_%=;\n\t" \
            "WAIT_DONE_%=:\n\t}" \
            :: "r"(_m), "r"(_p) : "memory"); \
    } \
} while (0)

#define TMA2D(smemaddr, tmapptr, cx, cy, mbar) \
    asm volatile( \
        "cp.async.bulk.tensor.2d.shared::cta.global.tile.mbarrier::complete_tx::bytes " \
        "[%0], [%1, {%2, %3}], [%4];" \
        :: "r"((uint32_t)(smemaddr)), "l"(tmapptr), "r"((int)(cx)), "r"((int)(cy)), \
           "r"((uint32_t)(mbar)) : "memory")

__device__ __forceinline__ void ldsm_x4(uint32_t* r, uint32_t addr) {
    asm volatile("ldmatrix.sync.aligned.m8n8.x4.shared.b16 {%0,%1,%2,%3}, [%4];"
        : "=r"(r[0]), "=r"(r[1]), "=r"(r[2]), "=r"(r[3]) : "r"(addr));
}

__device__ __forceinline__ void mma16816(float* d, const uint32_t* a, const uint32_t* b) {
    asm volatile(
        "mma.sync.aligned.m16n8k16.row.col.f32.f16.f16.f32 "
        "{%0,%1,%2,%3}, {%4,%5,%6,%7}, {%8,%9}, {%0,%1,%2,%3};"
        : "+f"(d[0]), "+f"(d[1]), "+f"(d[2]), "+f"(d[3])
        : "r"(a[0]), "r"(a[1]), "r"(a[2]), "r"(a[3]), "r"(b[0]), "r"(b[1]));
}

#define SWZ(o) ((o) ^ (((o) >> 3) & 0x70))

// ===================== HMMA GEMM =============================================
// C[M,Ntotal] = A[M,K] * B[N,K]^T, plain fp16 operands, fp32 acc.
// Tile 128(M) x 256(N), KC=64, 4-stage (48KB/stage) TMA pipeline,
// 8 warps (2x4), warp tile 64x64.
#define TILE_M 128
#define TILE_N 256
#define KC 64
#define NST 4
#define SOFF_A 0
#define SOFF_B 16384
#define STAGE 49152
#define GEMM_SMEM (1024 + NST * STAGE)

__global__ __launch_bounds__(256, 1)
void hmma_gemm(const __grid_constant__ CUtensorMap tA,
               const __grid_constant__ CUtensorMap tB,
               float* __restrict__ C, int Ntotal, int K, int epi)
{
    extern __shared__ __align__(1024) char smem[];
    const uint32_t sb = smem_to_u32(smem);
    const uint32_t sdata = sb + 1024;
    const int tid = threadIdx.x;
    const int wid = tid >> 5;
    const int lane = tid & 31;
    const int wm = wid >> 2;          // 0..1   (64 rows each)
    const int wn = wid & 3;           // 0..3   (64 cols each)
    const int bm = blockIdx.y * TILE_M;
    const int bn = blockIdx.x * TILE_N;

    uint32_t full[NST];
#pragma unroll
    for (int s = 0; s < NST; s++) full[s] = sb + 64 + s * 16;

    if (tid == 0) {
#pragma unroll
        for (int s = 0; s < NST; s++) MBARRIER_INIT(full[s], 1);
    }
    __syncthreads();

    const int NC = K / KC;

    if (tid == 0) {
#pragma unroll
        for (int s = 0; s < NST; s++) {
            if (s < NC) {
                uint32_t st = sdata + s * STAGE;
                MBARRIER_EXPECT_TX(full[s], STAGE);
                TMA2D(st + SOFF_A, &tA, s * KC, bm, full[s]);
                TMA2D(st + SOFF_B, &tB, s * KC, bn, full[s]);
            }
        }
    }

    uint32_t abase[4], bbase[4];
#pragma unroll
    for (int mt = 0; mt < 4; mt++) {
        int row = wm * 64 + mt * 16 + (lane & 15);
        abase[mt] = (uint32_t)(row * 128 + ((lane >> 4) * 16));
    }
#pragma unroll
    for (int q = 0; q < 4; q++) {
        int row = wn * 64 + q * 16 + ((lane >> 4) << 3) + (lane & 7);
        bbase[q] = (uint32_t)(row * 128 + (((lane >> 3) & 1) * 16));
    }

    float acc[4][8][4];
#pragma unroll
    for (int mt = 0; mt < 4; mt++)
#pragma unroll
        for (int nt = 0; nt < 8; nt++)
#pragma unroll
            for (int k = 0; k < 4; k++) acc[mt][nt][k] = 0.f;

    int ph[NST];
#pragma unroll
    for (int s = 0; s < NST; s++) ph[s] = 0;

    for (int c = 0; c < NC; c++) {
        const int s = c % NST;
        const uint32_t st = sdata + s * STAGE;
        MBARRIER_WAIT_PARITY(full[s], ph[s]);
        ph[s] ^= 1;

#pragma unroll
        for (int ks = 0; ks < 4; ks++) {
            const uint32_t kb = ks * 32;
            uint32_t af[4][4], bf[4][4];
#pragma unroll
            for (int mt = 0; mt < 4; mt++) {
                uint32_t off = SWZ(abase[mt] + kb);
                ldsm_x4(af[mt], st + SOFF_A + off);
            }
#pragma unroll
            for (int q = 0; q < 4; q++) {
                uint32_t off = SWZ(bbase[q] + kb);
                ldsm_x4(bf[q], st + SOFF_B + off);
            }
#pragma unroll
            for (int mt = 0; mt < 4; mt++) {
#pragma unroll
                for (int nt = 0; nt < 8; nt++) {
                    const uint32_t* Bf = &bf[nt >> 1][(nt & 1) * 2];
                    mma16816(acc[mt][nt], af[mt], Bf);
                }
            }
        }
        __syncthreads();   // all reads of stage s done
        if (tid == 0 && c + NST < NC) {
            MBARRIER_EXPECT_TX(full[s], STAGE);
            TMA2D(st + SOFF_A, &tA, (c + NST) * KC, bm, full[s]);
            TMA2D(st + SOFF_B, &tB, (c + NST) * KC, bn, full[s]);
        }
    }

    // epilogue
    const int g = lane >> 2;
    const int nq = (lane & 3) * 2;
#pragma unroll
    for (int mt = 0; mt < 4; mt++) {
        int r0 = bm + wm * 64 + mt * 16 + g;
#pragma unroll
        for (int nt = 0; nt < 8; nt++) {
            int cc = bn + wn * 64 + nt * 8 + nq;
            float2 v0 = make_float2(acc[mt][nt][0], acc[mt][nt][1]);
            float2 v1 = make_float2(acc[mt][nt][2], acc[mt][nt][3]);
            if (epi == 1) {
                v0.x = 1.f / (1.f + expf(-v0.x));
                v0.y = 1.f / (1.f + expf(-v0.y));
                v1.x = 1.f / (1.f + expf(-v1.x));
                v1.y = 1.f / (1.f + expf(-v1.y));
            }
            *reinterpret_cast<float2*>(C + (size_t)r0 * Ntotal + cc) = v0;
            *reinterpret_cast<float2*>(C + (size_t)(r0 + 8) * Ntotal + cc) = v1;
        }
    }
}

// ===================== fp32 -> fp16 plain convert ============================
__global__ __launch_bounds__(256)
void cvt_f16(const float* __restrict__ x, __half* __restrict__ y, int n)
{
    int i = (blockIdx.x * 256 + threadIdx.x) * 4;
    if (i >= n) return;
    float4 v = *reinterpret_cast<const float4*>(x + i);
    *reinterpret_cast<__half2*>(y + i)     = __halves2half2(__float2half_rn(v.x), __float2half_rn(v.y));
    *reinterpret_cast<__half2*>(y + i + 2) = __halves2half2(__float2half_rn(v.z), __float2half_rn(v.w));
}

// ---------------- conv(K=4, causal, depthwise) + SiLU + dt(softplus) -------
__global__ __launch_bounds__(256)
void conv_dt_kernel(const float* __restrict__ proj,
                    const float* __restrict__ cw,
                    const float* __restrict__ cb,
                    const float* __restrict__ dtw,
                    const float* __restrict__ dtb,
                    float* __restrict__ Xout,
                    float* __restrict__ dt_out)
{
    const int bl = blockIdx.x;
    const int l = bl % SEQLEN;
    __shared__ float sx[INNER];
    __shared__ float spart[NHEADS][4];

    const int tid = threadIdx.x;
    const float* base = proj + (size_t)bl * INNER;

    for (int c = tid; c < INNER; c += 256) {
        float accv = cb[c];
#pragma unroll
        for (int k = 0; k < D_CONV; k++) {
            int ll = l + k - (D_CONV - 1);
            float xv = (ll >= 0) ? base[(ptrdiff_t)(k - (D_CONV - 1)) * INNER + c] : 0.f;
            accv = fmaf(cw[c * D_CONV + k], xv, accv);
        }
        float s = accv / (1.f + expf(-accv));
        sx[c] = s;
        Xout[(size_t)bl * INNER + c] = s;
    }
    __syncthreads();

    {
        int h = tid >> 2;
        int part = tid & 3;
        float sum = 0.f;
        int p0 = part * 16;
#pragma unroll
        for (int p = 0; p < 16; p++)
            sum = fmaf(sx[h * HEADDIM + p0 + p], dtw[h * HEADDIM + p0 + p], sum);
        spart[h][part] = sum;
    }
    __syncthreads();
    if (tid < NHEADS) {
        float v = spart[tid][0] + spart[tid][1] + spart[tid][2] + spart[tid][3] + dtb[tid];
        float sp = (v > 20.f) ? v : log1pf(expf(v));
        dt_out[(size_t)bl * NHEADS + tid] = sp;
    }
}

// ---------------- SSM scan + output fusion (emits fp16) ---------------------
#define NSEG 16
#define SEG (SEQLEN / NSEG)     // 256

__global__ __launch_bounds__(1024, 1)
void scan_kernel(const float* __restrict__ X,
                 const float* __restrict__ dt,
                 const float* __restrict__ gate,
                 const float* __restrict__ A_log,
                 const float* __restrict__ Bv,
                 const float* __restrict__ Cv,
                 const float* __restrict__ Dv,
                 __half* __restrict__ comb)
{
    const int bh = blockIdx.x;
    const int h = bh % NHEADS;
    const int b = bh / NHEADS;
    const int p = threadIdx.x;
    const int s = threadIdx.y;

    const int hp = h * HEADDIM + p;
    const float acoef = -expf(A_log[hp]);
    const float Bc = Bv[hp];
    const float Cc = Cv[hp];
    const float Dc = Dv[hp];

    const size_t baseX = (size_t)b * SEQLEN * INNER + (size_t)h * HEADDIM + p;
    const size_t baseDt = (size_t)b * SEQLEN * NHEADS + h;
    const int l0 = s * SEG;

    __shared__ float agg_a[NSEG][HEADDIM];
    __shared__ float agg_u[NSEG][HEADDIM];
    __shared__ float pre[NSEG][HEADDIM];

    float ap = 1.f, ss = 0.f;
    for (int i = 0; i < SEG; i++) {
        int l = l0 + i;
        float d = dt[baseDt + (size_t)l * NHEADS];
        float xv = X[baseX + (size_t)l * INNER];
        float a = expf(d * acoef);
        float u = d * Bc * xv;
        ap *= a;
        ss = fmaf(a, ss, u);
    }
    agg_a[s][p] = ap;
    agg_u[s][p] = ss;
    __syncthreads();

    if (s == 0) {
        float st = 0.f;
#pragma unroll
        for (int j = 0; j < NSEG; j++) {
            pre[j][p] = st;
            st = fmaf(agg_a[j][p], st, agg_u[j][p]);
        }
    }
    __syncthreads();

    float sprev = pre[s][p];
    for (int i = 0; i < SEG; i++) {
        int l = l0 + i;
        float d = dt[baseDt + (size_t)l * NHEADS];
        size_t idx = baseX + (size_t)l * INNER;
        float xv = X[idx];
        float a = expf(d * acoef);
        float u = d * Bc * xv;
        sprev = fmaf(a, sprev, u);
        float y = fmaf(Cc, sprev, Dc * xv) * gate[idx];
        comb[idx] = __float2half_rn(y);
    }
}

// ===================== host side ============================================
typedef CUresult (*TmEncodeFn)(CUtensorMap*, CUtensorMapDataType, cuuint32_t,
                               void*, const cuuint64_t*, const cuuint64_t*,
                               const cuuint32_t*, const cuuint32_t*,
                               CUtensorMapInterleave, CUtensorMapSwizzle,
                               CUtensorMapL2promotion, CUtensorMapFloatOOBfill);

static void make_tm(TmEncodeFn fn, CUtensorMap* tm, const void* ptr,
                    int rows, int K, int boxRows)
{
    cuuint64_t dims[2]    = {(cuuint64_t)K, (cuuint64_t)rows};
    cuuint64_t strides[1] = {(cuuint64_t)K * 2};
    cuuint32_t box[2]     = {64u, (cuuint32_t)boxRows};
    cuuint32_t es[2]      = {1u, 1u};
    fn(tm, CU_TENSOR_MAP_DATA_TYPE_FLOAT16, 2, (void*)ptr,
       dims, strides, box, es,
       CU_TENSOR_MAP_INTERLEAVE_NONE, CU_TENSOR_MAP_SWIZZLE_128B,
       CU_TENSOR_MAP_L2_PROMOTION_L2_128B, CU_TENSOR_MAP_FLOAT_OOB_FILL_NONE);
}

extern "C" void kernel_launch(void* const* d_in, const int* in_sizes, int n_in,
                              void* d_out, int out_size)
{
    const float* hidden = (const float*)d_in[0];
    const float* in_w   = (const float*)d_in[1];
    const float* gate_w = (const float*)d_in[2];
    const float* out_w  = (const float*)d_in[3];
    const float* conv_w = (const float*)d_in[4];
    const float* conv_b = (const float*)d_in[5];
    const float* dt_w   = (const float*)d_in[6];
    const float* dt_b   = (const float*)d_in[7];
    const float* A_log  = (const float*)d_in[8];
    const float* Bv     = (const float*)d_in[9];
    const float* Cv     = (const float*)d_in[10];
    const float* Dv     = (const float*)d_in[11];
    float* out          = (float*)d_out;

    float *proj, *gatebuf, *xbuf, *dtbuf;
    __half *hx, *iw, *gw, *ow, *cbuf;
    cudaGetSymbolAddress((void**)&proj,    g_proj);
    cudaGetSymbolAddress((void**)&gatebuf, g_gate);
    cudaGetSymbolAddress((void**)&xbuf,    g_x);
    cudaGetSymbolAddress((void**)&dtbuf,   g_dt);
    cudaGetSymbolAddress((void**)&hx, g_hx);
    cudaGetSymbolAddress((void**)&iw, g_iw);
    cudaGetSymbolAddress((void**)&gw, g_gw);
    cudaGetSymbolAddress((void**)&ow, g_ow);
    cudaGetSymbolAddress((void**)&cbuf, g_cb);

    TmEncodeFn enc = nullptr;
    {
        void* p = nullptr;
        cudaDriverEntryPointQueryResult qr;
        cudaGetDriverEntryPointByVersion("cuTensorMapEncodeTiled", &p, 12000,
                                         cudaEnableDefault, &qr);
        enc = (TmEncodeFn)p;
    }

    // converts
    {
        int n;
        n = BL * D_MODEL;        cvt_f16<<<n / 1024, 256>>>(hidden, hx, n);
        n = INNER * D_MODEL;     cvt_f16<<<n / 1024, 256>>>(in_w,   iw, n);
        n = INNER * D_MODEL;     cvt_f16<<<n / 1024, 256>>>(gate_w, gw, n);
        n = D_MODEL * INNER;     cvt_f16<<<n / 1024, 256>>>(out_w,  ow, n);
    }

    CUtensorMap tm_hx, tm_iw, tm_gw, tm_ow, tm_cb;
    make_tm(enc, &tm_hx, hx, BL,      D_MODEL, 128);
    make_tm(enc, &tm_iw, iw, INNER,   D_MODEL, 256);
    make_tm(enc, &tm_gw, gw, INNER,   D_MODEL, 256);
    make_tm(enc, &tm_ow, ow, D_MODEL, INNER,   256);
    make_tm(enc, &tm_cb, cbuf, BL,    INNER,   128);

    cudaFuncSetAttribute(hmma_gemm, cudaFuncAttributeMaxDynamicSharedMemorySize, GEMM_SMEM);

    // 1) in_proj: (8192 x 2048) @ (4096 x 2048)^T -> proj
    {
        dim3 grid(INNER / TILE_N, BL / TILE_M);
        hmma_gemm<<<grid, 256, GEMM_SMEM>>>(tm_hx, tm_iw, proj, INNER, D_MODEL, 0);
    }
    // 2) gate + sigmoid epilogue
    {
        dim3 grid(INNER / TILE_N, BL / TILE_M);
        hmma_gemm<<<grid, 256, GEMM_SMEM>>>(tm_hx, tm_gw, gatebuf, INNER, D_MODEL, 1);
    }
    // 3) conv + silu + dt
    conv_dt_kernel<<<BL, 256>>>(proj, conv_w, conv_b, dt_w, dt_b, xbuf, dtbuf);
    // 4) SSM scan fused with y, gate, fp16 convert
    {
        dim3 blk(HEADDIM, NSEG);
        scan_kernel<<<BATCH * NHEADS, blk>>>(xbuf, dtbuf, gatebuf, A_log, Bv, Cv, Dv, cbuf);
    }
    // 5) out_proj: (8192 x 4096) @ (2048 x 4096)^T -> out
    {
        dim3 grid(D_MODEL / TILE_N, BL / TILE_M);
        hmma_gemm<<<grid, 256, GEMM_SMEM>>>(tm_cb, tm_ow, out, D_MODEL, INNER, 0);
    }
}

// round 7
// speedup vs baseline: 7.4328x; 1.0061x over previous
#include <cuda.h>
#include <cuda_runtime.h>
#include <cuda_fp16.h>
#include <math.h>

#define D_MODEL 2048
#define INNER   4096
#define NHEADS  64
#define HEADDIM 64
#define D_CONV  4
#define BATCH   2
#define SEQLEN  4096
#define BL (BATCH * SEQLEN)      // 8192

// ---------------- scratch (device globals; no allocation allowed) ----------
__device__ float g_proj[(size_t)BL * INNER];            // in_proj output (fp32)
__device__ float g_gate[(size_t)BL * INNER];            // sigmoid(gate_proj)
__device__ float g_x[(size_t)BL * INNER];               // conv+silu output X
__device__ float g_dt[(size_t)BL * NHEADS];             // softplus(dt)

__device__ __half g_hx[(size_t)BL * D_MODEL];           // hidden fp16
__device__ __half g_iw[(size_t)INNER * D_MODEL];        // in_w fp16
__device__ __half g_gw[(size_t)INNER * D_MODEL];        // gate_w fp16
__device__ __half g_ow[(size_t)D_MODEL * INNER];        // out_w fp16
__device__ __half g_cb[(size_t)BL * INNER];             // comb fp16

// ===================== PTX helpers ==========================================
__device__ __forceinline__ uint32_t smem_to_u32(const void* smem_ptr) {
    uint32_t addr;
    asm("{ .reg .u64 tmp; cvta.to.shared.u64 tmp, %1; cvt.u32.u64 %0, tmp; }"
        : "=r"(addr) : "l"(smem_ptr));
    return addr;
}

#define MBARRIER_INIT(mbar, count) \
    asm volatile("mbarrier.init.shared.b64 [%0], %1;" \
        :: "r"((uint32_t)(mbar)), "r"((uint32_t)(count)) : "memory")

#define MBARRIER_EXPECT_TX(mbar, bytes) \
    asm volatile("mbarrier.arrive.expect_tx.shared.b64 _, [%0], %1;" \
        :: "r"((uint32_t)(mbar)), "r"((uint32_t)(bytes)) : "memory")

#define MBARRIER_WAIT_PARITY(mbar, parity) do { \
    uint32_t _m = (uint32_t)(mbar); uint32_t _p = (uint32_t)(parity); uint32_t _d; \
    asm volatile( \
        "{\n\t.reg .pred p;\n\t" \
        "mbarrier.try_wait.parity.acquire.cta.shared::cta.b64 p, [%1], %2;\n\t" \
        "selp.b32 %0, 1, 0, p;\n\t}" \
        : "=r"(_d) : "r"(_m), "r"(_p) : "memory"); \
    if (!_d) { \
        asm volatile( \
            "{\n\t.reg .pred P1;\n\t" \
            "WAIT_LOOP_%=:\n\t" \
            "mbarrier.try_wait.parity.acquire.cta.shared::cta.b64 P1, [%0], %1, 0x989680;\n\t" \
            "@P1 bra.uni WAIT_DONE_%=;\n\t" \
            "bra.uni WAIT_LOOP_%=;\n\t" \
            "WAIT_DONE_%=:\n\t}" \
            :: "r"(_m), "r"(_p) : "memory"); \
    } \
} while (0)

#define TMA2D(smemaddr, tmapptr, cx, cy, mbar) \
    asm volatile( \
        "cp.async.bulk.tensor.2d.shared::cta.global.tile.mbarrier::complete_tx::bytes " \
        "[%0], [%1, {%2, %3}], [%4];" \
        :: "r"((uint32_t)(smemaddr)), "l"(tmapptr), "r"((int)(cx)), "r"((int)(cy)), \
           "r"((uint32_t)(mbar)) : "memory")

__device__ __forceinline__ void ldsm_x4(uint32_t* r, uint32_t addr) {
    asm volatile("ldmatrix.sync.aligned.m8n8.x4.shared.b16 {%0,%1,%2,%3}, [%4];"
        : "=r"(r[0]), "=r"(r[1]), "=r"(r[2]), "=r"(r[3]) : "r"(addr));
}

__device__ __forceinline__ void mma16816(float* d, const uint32_t* a, const uint32_t* b) {
    asm volatile(
        "mma.sync.aligned.m16n8k16.row.col.f32.f16.f16.f32 "
        "{%0,%1,%2,%3}, {%4,%5,%6,%7}, {%8,%9}, {%0,%1,%2,%3};"
        : "+f"(d[0]), "+f"(d[1]), "+f"(d[2]), "+f"(d[3])
        : "r"(a[0]), "r"(a[1]), "r"(a[2]), "r"(a[3]), "r"(b[0]), "r"(b[1]));
}

#define SWZ(o) ((o) ^ (((o) >> 3) & 0x70))

// ===================== HMMA GEMM =============================================
// C[M,Ntotal] = A[M,K] * B[N,K]^T, plain fp16 operands, fp32 acc.
// Tile 128(M) x 256(N), KC=64, 4-stage (48KB/stage) TMA pipeline,
// 512 threads / 16 warps (4x4), warp tile 32x64.
#define TILE_M 128
#define TILE_N 256
#define KC 64
#define NST 4
#define SOFF_A 0
#define SOFF_B 16384
#define STAGE 49152
#define GEMM_SMEM (1024 + NST * STAGE)

__global__ __launch_bounds__(512, 1)
void hmma_gemm(const __grid_constant__ CUtensorMap tA,
               const __grid_constant__ CUtensorMap tB,
               float* __restrict__ C, int Ntotal, int K, int epi)
{
    extern __shared__ __align__(1024) char smem[];
    const uint32_t sb = smem_to_u32(smem);
    const uint32_t sdata = sb + 1024;
    const int tid = threadIdx.x;
    const int wid = tid >> 5;
    const int lane = tid & 31;
    const int wm = wid >> 2;          // 0..3   (32 rows each)
    const int wn = wid & 3;           // 0..3   (64 cols each)
    const int bm = blockIdx.y * TILE_M;
    const int bn = blockIdx.x * TILE_N;

    uint32_t full[NST];
#pragma unroll
    for (int s = 0; s < NST; s++) full[s] = sb + 64 + s * 16;

    if (tid == 0) {
#pragma unroll
        for (int s = 0; s < NST; s++) MBARRIER_INIT(full[s], 1);
    }
    __syncthreads();

    const int NC = K / KC;

    if (tid == 0) {
#pragma unroll
        for (int s = 0; s < NST; s++) {
            if (s < NC) {
                uint32_t st = sdata + s * STAGE;
                MBARRIER_EXPECT_TX(full[s], STAGE);
                TMA2D(st + SOFF_A, &tA, s * KC, bm, full[s]);
                TMA2D(st + SOFF_B, &tB, s * KC, bn, full[s]);
            }
        }
    }

    uint32_t abase[2], bbase[4];
#pragma unroll
    for (int mt = 0; mt < 2; mt++) {
        int row = wm * 32 + mt * 16 + (lane & 15);
        abase[mt] = (uint32_t)(row * 128 + ((lane >> 4) * 16));
    }
#pragma unroll
    for (int q = 0; q < 4; q++) {
        int row = wn * 64 + q * 16 + ((lane >> 4) << 3) + (lane & 7);
        bbase[q] = (uint32_t)(row * 128 + (((lane >> 3) & 1) * 16));
    }

    float acc[2][8][4];
#pragma unroll
    for (int mt = 0; mt < 2; mt++)
#pragma unroll
        for (int nt = 0; nt < 8; nt++)
#pragma unroll
            for (int k = 0; k < 4; k++) acc[mt][nt][k] = 0.f;

    int ph[NST];
#pragma unroll
    for (int s = 0; s < NST; s++) ph[s] = 0;

    for (int c = 0; c < NC; c++) {
        const int s = c % NST;
        const uint32_t st = sdata + s * STAGE;
        MBARRIER_WAIT_PARITY(full[s], ph[s]);
        ph[s] ^= 1;

#pragma unroll
        for (int ks = 0; ks < 4; ks++) {
            const uint32_t kb = ks * 32;
            uint32_t af[2][4], bf[4][4];
#pragma unroll
            for (int mt = 0; mt < 2; mt++) {
                uint32_t off = SWZ(abase[mt] + kb);
                ldsm_x4(af[mt], st + SOFF_A + off);
            }
#pragma unroll
            for (int q = 0; q < 4; q++) {
                uint32_t off = SWZ(bbase[q] + kb);
                ldsm_x4(bf[q], st + SOFF_B + off);
            }
#pragma unroll
            for (int mt = 0; mt < 2; mt++) {
#pragma unroll
                for (int nt = 0; nt < 8; nt++) {
                    const uint32_t* Bf = &bf[nt >> 1][(nt & 1) * 2];
                    mma16816(acc[mt][nt], af[mt], Bf);
                }
            }
        }
        __syncthreads();   // all reads of stage s done
        if (tid == 0 && c + NST < NC) {
            MBARRIER_EXPECT_TX(full[s], STAGE);
            TMA2D(st + SOFF_A, &tA, (c + NST) * KC, bm, full[s]);
            TMA2D(st + SOFF_B, &tB, (c + NST) * KC, bn, full[s]);
        }
    }

    // epilogue
    const int g = lane >> 2;
    const int nq = (lane & 3) * 2;
#pragma unroll
    for (int mt = 0; mt < 2; mt++) {
        int r0 = bm + wm * 32 + mt * 16 + g;
#pragma unroll
        for (int nt = 0; nt < 8; nt++) {
            int cc = bn + wn * 64 + nt * 8 + nq;
            float2 v0 = make_float2(acc[mt][nt][0], acc[mt][nt][1]);
            float2 v1 = make_float2(acc[mt][nt][2], acc[mt][nt][3]);
            if (epi == 1) {
                v0.x = 1.f / (1.f + expf(-v0.x));
                v0.y = 1.f / (1.f + expf(-v0.y));
                v1.x = 1.f / (1.f + expf(-v1.x));
                v1.y = 1.f / (1.f + expf(-v1.y));
            }
            *reinterpret_cast<float2*>(C + (size_t)r0 * Ntotal + cc) = v0;
            *reinterpret_cast<float2*>(C + (size_t)(r0 + 8) * Ntotal + cc) = v1;
        }
    }
}

// ===================== fp32 -> fp16 plain convert ============================
__global__ __launch_bounds__(256)
void cvt_f16(const float* __restrict__ x, __half* __restrict__ y, int n)
{
    int i = (blockIdx.x * 256 + threadIdx.x) * 4;
    if (i >= n) return;
    float4 v = *reinterpret_cast<const float4*>(x + i);
    *reinterpret_cast<__half2*>(y + i)     = __halves2half2(__float2half_rn(v.x), __float2half_rn(v.y));
    *reinterpret_cast<__half2*>(y + i + 2) = __halves2half2(__float2half_rn(v.z), __float2half_rn(v.w));
}

// ---------------- conv(K=4, causal, depthwise) + SiLU + dt(softplus) -------
__global__ __launch_bounds__(256)
void conv_dt_kernel(const float* __restrict__ proj,
                    const float* __restrict__ cw,
                    const float* __restrict__ cb,
                    const float* __restrict__ dtw,
                    const float* __restrict__ dtb,
                    float* __restrict__ Xout,
                    float* __restrict__ dt_out)
{
    const int bl = blockIdx.x;
    const int l = bl % SEQLEN;
    __shared__ float sx[INNER];
    __shared__ float spart[NHEADS][4];

    const int tid = threadIdx.x;
    const float* base = proj + (size_t)bl * INNER;

    for (int c = tid; c < INNER; c += 256) {
        float accv = cb[c];
#pragma unroll
        for (int k = 0; k < D_CONV; k++) {
            int ll = l + k - (D_CONV - 1);
            float xv = (ll >= 0) ? base[(ptrdiff_t)(k - (D_CONV - 1)) * INNER + c] : 0.f;
            accv = fmaf(cw[c * D_CONV + k], xv, accv);
        }
        float s = accv / (1.f + expf(-accv));
        sx[c] = s;
        Xout[(size_t)bl * INNER + c] = s;
    }
    __syncthreads();

    {
        int h = tid >> 2;
        int part = tid & 3;
        float sum = 0.f;
        int p0 = part * 16;
#pragma unroll
        for (int p = 0; p < 16; p++)
            sum = fmaf(sx[h * HEADDIM + p0 + p], dtw[h * HEADDIM + p0 + p], sum);
        spart[h][part] = sum;
    }
    __syncthreads();
    if (tid < NHEADS) {
        float v = spart[tid][0] + spart[tid][1] + spart[tid][2] + spart[tid][3] + dtb[tid];
        float sp = (v > 20.f) ? v : log1pf(expf(v));
        dt_out[(size_t)bl * NHEADS + tid] = sp;
    }
}

// ---------------- SSM scan + output fusion (emits fp16) ---------------------
#define NSEG 16
#define SEG (SEQLEN / NSEG)     // 256

__global__ __launch_bounds__(1024, 1)
void scan_kernel(const float* __restrict__ X,
                 const float* __restrict__ dt,
                 const float* __restrict__ gate,
                 const float* __restrict__ A_log,
                 const float* __restrict__ Bv,
                 const float* __restrict__ Cv,
                 const float* __restrict__ Dv,
                 __half* __restrict__ comb)
{
    const int bh = blockIdx.x;
    const int h = bh % NHEADS;
    const int b = bh / NHEADS;
    const int p = threadIdx.x;
    const int s = threadIdx.y;

    const int hp = h * HEADDIM + p;
    const float acoef = -expf(A_log[hp]);
    const float Bc = Bv[hp];
    const float Cc = Cv[hp];
    const float Dc = Dv[hp];

    const size_t baseX = (size_t)b * SEQLEN * INNER + (size_t)h * HEADDIM + p;
    const size_t baseDt = (size_t)b * SEQLEN * NHEADS + h;
    const int l0 = s * SEG;

    __shared__ float agg_a[NSEG][HEADDIM];
    __shared__ float agg_u[NSEG][HEADDIM];
    __shared__ float pre[NSEG][HEADDIM];

    float ap = 1.f, ss = 0.f;
    for (int i = 0; i < SEG; i++) {
        int l = l0 + i;
        float d = dt[baseDt + (size_t)l * NHEADS];
        float xv = X[baseX + (size_t)l * INNER];
        float a = expf(d * acoef);
        float u = d * Bc * xv;
        ap *= a;
        ss = fmaf(a, ss, u);
    }
    agg_a[s][p] = ap;
    agg_u[s][p] = ss;
    __syncthreads();

    if (s == 0) {
        float st = 0.f;
#pragma unroll
        for (int j = 0; j < NSEG; j++) {
            pre[j][p] = st;
            st = fmaf(agg_a[j][p], st, agg_u[j][p]);
        }
    }
    __syncthreads();

    float sprev = pre[s][p];
    for (int i = 0; i < SEG; i++) {
        int l = l0 + i;
        float d = dt[baseDt + (size_t)l * NHEADS];
        size_t idx = baseX + (size_t)l * INNER;
        float xv = X[idx];
        float a = expf(d * acoef);
        float u = d * Bc * xv;
        sprev = fmaf(a, sprev, u);
        float y = fmaf(Cc, sprev, Dc * xv) * gate[idx];
        comb[idx] = __float2half_rn(y);
    }
}

// ===================== host side ============================================
typedef CUresult (*TmEncodeFn)(CUtensorMap*, CUtensorMapDataType, cuuint32_t,
                               void*, const cuuint64_t*, const cuuint64_t*,
                               const cuuint32_t*, const cuuint32_t*,
                               CUtensorMapInterleave, CUtensorMapSwizzle,
                               CUtensorMapL2promotion, CUtensorMapFloatOOBfill);

static void make_tm(TmEncodeFn fn, CUtensorMap* tm, const void* ptr,
                    int rows, int K, int boxRows)
{
    cuuint64_t dims[2]    = {(cuuint64_t)K, (cuuint64_t)rows};
    cuuint64_t strides[1] = {(cuuint64_t)K * 2};
    cuuint32_t box[2]     = {64u, (cuuint32_t)boxRows};
    cuuint32_t es[2]      = {1u, 1u};
    fn(tm, CU_TENSOR_MAP_DATA_TYPE_FLOAT16, 2, (void*)ptr,
       dims, strides, box, es,
       CU_TENSOR_MAP_INTERLEAVE_NONE, CU_TENSOR_MAP_SWIZZLE_128B,
       CU_TENSOR_MAP_L2_PROMOTION_L2_128B, CU_TENSOR_MAP_FLOAT_OOB_FILL_NONE);
}

extern "C" void kernel_launch(void* const* d_in, const int* in_sizes, int n_in,
                              void* d_out, int out_size)
{
    const float* hidden = (const float*)d_in[0];
    const float* in_w   = (const float*)d_in[1];
    const float* gate_w = (const float*)d_in[2];
    const float* out_w  = (const float*)d_in[3];
    const float* conv_w = (const float*)d_in[4];
    const float* conv_b = (const float*)d_in[5];
    const float* dt_w   = (const float*)d_in[6];
    const float* dt_b   = (const float*)d_in[7];
    const float* A_log  = (const float*)d_in[8];
    const float* Bv     = (const float*)d_in[9];
    const float* Cv     = (const float*)d_in[10];
    const float* Dv     = (const float*)d_in[11];
    float* out          = (float*)d_out;

    float *proj, *gatebuf, *xbuf, *dtbuf;
    __half *hx, *iw, *gw, *ow, *cbuf;
    cudaGetSymbolAddress((void**)&proj,    g_proj);
    cudaGetSymbolAddress((void**)&gatebuf, g_gate);
    cudaGetSymbolAddress((void**)&xbuf,    g_x);
    cudaGetSymbolAddress((void**)&dtbuf,   g_dt);
    cudaGetSymbolAddress((void**)&hx, g_hx);
    cudaGetSymbolAddress((void**)&iw, g_iw);
    cudaGetSymbolAddress((void**)&gw, g_gw);
    cudaGetSymbolAddress((void**)&ow, g_ow);
    cudaGetSymbolAddress((void**)&cbuf, g_cb);

    TmEncodeFn enc = nullptr;
    {
        void* p = nullptr;
        cudaDriverEntryPointQueryResult qr;
        cudaGetDriverEntryPointByVersion("cuTensorMapEncodeTiled", &p, 12000,
                                         cudaEnableDefault, &qr);
        enc = (TmEncodeFn)p;
    }

    // converts
    {
        int n;
        n = BL * D_MODEL;        cvt_f16<<<n / 1024, 256>>>(hidden, hx, n);
        n = INNER * D_MODEL;     cvt_f16<<<n / 1024, 256>>>(in_w,   iw, n);
        n = INNER * D_MODEL;     cvt_f16<<<n / 1024, 256>>>(gate_w, gw, n);
        n = D_MODEL * INNER;     cvt_f16<<<n / 1024, 256>>>(out_w,  ow, n);
    }

    CUtensorMap tm_hx, tm_iw, tm_gw, tm_ow, tm_cb;
    make_tm(enc, &tm_hx, hx, BL,      D_MODEL, 128);
    make_tm(enc, &tm_iw, iw, INNER,   D_MODEL, 256);
    make_tm(enc, &tm_gw, gw, INNER,   D_MODEL, 256);
    make_tm(enc, &tm_ow, ow, D_MODEL, INNER,   256);
    make_tm(enc, &tm_cb, cbuf, BL,    INNER,   128);

    cudaFuncSetAttribute(hmma_gemm, cudaFuncAttributeMaxDynamicSharedMemorySize, GEMM_SMEM);

    // 1) in_proj: (8192 x 2048) @ (4096 x 2048)^T -> proj
    {
        dim3 grid(INNER / TILE_N, BL / TILE_M);
        hmma_gemm<<<grid, 512, GEMM_SMEM>>>(tm_hx, tm_iw, proj, INNER, D_MODEL, 0);
    }
    // 2) gate + sigmoid epilogue
    {
        dim3 grid(INNER / TILE_N, BL / TILE_M);
        hmma_gemm<<<grid, 512, GEMM_SMEM>>>(tm_hx, tm_gw, gatebuf, INNER, D_MODEL, 1);
    }
    // 3) conv + silu + dt
    conv_dt_kernel<<<BL, 256>>>(proj, conv_w, conv_b, dt_w, dt_b, xbuf, dtbuf);
    // 4) SSM scan fused with y, gate, fp16 convert
    {
        dim3 blk(HEADDIM, NSEG);
        scan_kernel<<<BATCH * NHEADS, blk>>>(xbuf, dtbuf, gatebuf, A_log, Bv, Cv, Dv, cbuf);
    }
    // 5) out_proj: (8192 x 4096) @ (2048 x 4096)^T -> out
    {
        dim3 grid(D_MODEL / TILE_N, BL / TILE_M);
        hmma_gemm<<<grid, 512, GEMM_SMEM>>>(tm_cb, tm_ow, out, D_MODEL, INNER, 0);
    }
}